// round 13
// baseline (speedup 1.0000x reference)
#include <cuda_runtime.h>
#include <math.h>

#define HH 512
#define WW 512
#define NB 2
#define HWSZ (HH*WW)          // 262144
#define NHW (NB*HWSZ)         // 524288

// ---------------- scratch (device globals; no allocation allowed) -------------
__device__ float g_feat [NB*32*HWSZ];
__device__ float g_aux  [NB*32*HWSZ];
__device__ float g_auxb1[NB*32*HWSZ];
__device__ float g_z    [NHW];
__device__ float g_inp  [NHW];
__device__ float g_xm25 [NB*25*HWSZ];
__device__ float g_part [32*512*2];
__device__ float g_scale1[32], g_shift1[32];
__device__ unsigned g_hist[4][256];
__device__ unsigned g_prefix[4];
__device__ int      g_remain[4];
__device__ float    g_thr[4];

// ---------------- fused dual 3x3 conv (3->32 twice): 16 oc x 4 rows/thread ----
template<bool ERASE>
__global__ __launch_bounds__(256) void dualconv3_k(
    const float* __restrict__ img, const float* __restrict__ seg,
    const float* __restrict__ w1, const float* __restrict__ wa,
    float* __restrict__ feat, float* __restrict__ aux)
{
    __shared__ float tile[2][34][34];
    __shared__ float wsm[16*27];
    const int tid = threadIdx.y*32 + threadIdx.x;
    const int tx = threadIdx.x, ty = threadIdx.y;
    const int grp = blockIdx.z & 3;
    const int n   = blockIdx.z >> 2;
    const int oc0 = grp*8;
    const int x0 = blockIdx.x*32, y0 = blockIdx.y*32;
    const int TSZ = 34*34;
    const int NLD = 5;

    for (int i = tid; i < 16*27; i += 256){
        int o = i/27, rr = i - o*27;
        wsm[i] = (o < 8) ? w1[(oc0+o)*27 + rr] : wa[(oc0+o-8)*27 + rr];
    }

    int off[NLD]; unsigned vmask = 0u, emask = 0u;
    #pragma unroll
    for (int j=0;j<NLD;j++){
        int i = tid + j*256;
        int yy = i/34, xx = i - yy*34;
        int gy = y0+yy-1, gx = x0+xx-1;
        bool v = (i < TSZ) && ((unsigned)gy < HH) && ((unsigned)gx < WW);
        off[j] = v ? (gy*WW + gx) : 0;
        if (v) vmask |= (1u<<j);
    }
    if (ERASE){
        float t0 = g_thr[n*2+0], t1 = g_thr[n*2+1];
        #pragma unroll
        for (int j=0;j<NLD;j++){
            if ((vmask>>j)&1u){
                float s0 = seg[((size_t)(n*2+0))*HWSZ + off[j]];
                float s1 = seg[((size_t)(n*2+1))*HWSZ + off[j]];
                if (s0 > t0 || s1 > t1) emask |= (1u<<j);
            }
        }
    }

    {
        const float* src = img + (size_t)(n*3)*HWSZ;
        float rld[NLD];
        #pragma unroll
        for (int j=0;j<NLD;j++)
            rld[j] = (((vmask>>j)&1u) && !((emask>>j)&1u)) ? src[off[j]] : 0.f;
        float* tb = &tile[0][0][0];
        #pragma unroll
        for (int j=0;j<NLD;j++){ int i = tid + j*256; if (i < TSZ) tb[i] = rld[j]; }
    }
    __syncthreads();

    float acc[16][4];
    #pragma unroll
    for (int o=0;o<16;o++)
        #pragma unroll
        for (int k=0;k<4;k++) acc[o][k]=0.f;

    for (int c = 0; c < 3; c++){
        const int cur = c & 1;
        float rld[NLD];
        if (c+1 < 3){
            const float* src = img + (size_t)(n*3 + c+1)*HWSZ;
            #pragma unroll
            for (int j=0;j<NLD;j++)
                rld[j] = (((vmask>>j)&1u) && !((emask>>j)&1u)) ? src[off[j]] : 0.f;
        }
        #pragma unroll
        for (int r=0;r<3;r++)
        #pragma unroll
        for (int s=0;s<3;s++){
            float wv[16];
            #pragma unroll
            for (int o=0;o<16;o++) wv[o] = wsm[o*27 + c*9 + r*3 + s];
            #pragma unroll
            for (int k=0;k<4;k++){
                float v = tile[cur][ty + 8*k + r][tx + s];
                #pragma unroll
                for (int o=0;o<16;o++) acc[o][k] = fmaf(wv[o], v, acc[o][k]);
            }
        }
        if (c+1 < 3){
            float* tb = &tile[cur^1][0][0];
            #pragma unroll
            for (int j=0;j<NLD;j++){ int i = tid + j*256; if (i < TSZ) tb[i] = rld[j]; }
        }
        __syncthreads();
    }

    #pragma unroll
    for (int o=0;o<16;o++)
    #pragma unroll
    for (int k=0;k<4;k++){
        float v = fmaxf(acc[o][k], 0.f);
        size_t idx = (size_t)(y0+ty+8*k)*WW + x0 + tx;
        if (o < 8) feat[((size_t)(n*32 + oc0 + o  ))*HWSZ + idx] = v;
        else       aux [((size_t)(n*32 + oc0 + o-8))*HWSZ + idx] = v;
    }
}

// ---------------- 32->32 3x3 conv: 16 oc x 4 rows/thread, fused BN partials ----
// tile 32x32; 2 oc-groups; 3 blocks/SM (reg-capped), offsets recomputed/channel.
__global__ __launch_bounds__(256,3) void conv32_k(
    const float* __restrict__ in, const float* __restrict__ wt,
    float* __restrict__ out)
{
    __shared__ float tile[2][34][34];
    __shared__ float wsm[16*32*9];
    const int tid = threadIdx.y*32 + threadIdx.x;
    const int tx = threadIdx.x, ty = threadIdx.y;
    const int grp = blockIdx.z & 1;
    const int n   = blockIdx.z >> 1;
    const int oc0 = grp*16;
    const int x0 = blockIdx.x*32, y0 = blockIdx.y*32;
    const int TSZ = 34*34;
    const int NLD = 5;

    for (int i = tid; i < 16*32*9; i += 256) wsm[i] = wt[oc0*32*9 + i];

    {
        const float* src = in + (size_t)(n*32)*HWSZ;
        float rld[NLD];
        #pragma unroll
        for (int j=0;j<NLD;j++){
            int i = tid + j*256;
            int yy = i/34, xx = i - yy*34;
            int gy = y0+yy-1, gx = x0+xx-1;
            bool v = (i < TSZ) && ((unsigned)gy < HH) && ((unsigned)gx < WW);
            rld[j] = v ? src[gy*WW + gx] : 0.f;
        }
        float* tb = &tile[0][0][0];
        #pragma unroll
        for (int j=0;j<NLD;j++){ int i = tid + j*256; if (i < TSZ) tb[i] = rld[j]; }
    }
    __syncthreads();

    float acc[16][4];
    #pragma unroll
    for (int o=0;o<16;o++)
        #pragma unroll
        for (int k=0;k<4;k++) acc[o][k]=0.f;

    for (int c = 0; c < 32; c++){
        const int cur = c & 1;
        float rld[NLD];
        if (c+1 < 32){
            const float* src = in + (size_t)(n*32 + c+1)*HWSZ;
            #pragma unroll
            for (int j=0;j<NLD;j++){
                int i = tid + j*256;
                int yy = i/34, xx = i - yy*34;
                int gy = y0+yy-1, gx = x0+xx-1;
                bool v = (i < TSZ) && ((unsigned)gy < HH) && ((unsigned)gx < WW);
                rld[j] = v ? src[gy*WW + gx] : 0.f;
            }
        }
        #pragma unroll
        for (int r=0;r<3;r++)
        #pragma unroll
        for (int s=0;s<3;s++){
            float wv[16];
            #pragma unroll
            for (int o=0;o<16;o++) wv[o] = wsm[(o*32+c)*9 + r*3 + s];
            #pragma unroll
            for (int k=0;k<4;k++){
                float v = tile[cur][ty + 8*k + r][tx + s];
                #pragma unroll
                for (int o=0;o<16;o++) acc[o][k] = fmaf(wv[o], v, acc[o][k]);
            }
        }
        if (c+1 < 32){
            float* tb = &tile[cur^1][0][0];
            #pragma unroll
            for (int j=0;j<NLD;j++){ int i = tid + j*256; if (i < TSZ) tb[i] = rld[j]; }
        }
        __syncthreads();
    }

    #pragma unroll
    for (int o=0;o<16;o++)
    #pragma unroll
    for (int k=0;k<4;k++)
        out[((size_t)(n*32 + oc0 + o))*HWSZ + (size_t)(y0+ty+8*k)*WW + x0 + tx] = acc[o][k];

    // deterministic per-block BN partials (one oc at a time: no reg blowup)
    float* red = &tile[0][0][0];
    #pragma unroll
    for (int o=0;o<16;o++){
        float sv=0.f, qv=0.f;
        #pragma unroll
        for (int k=0;k<4;k++){ float v=acc[o][k]; sv+=v; qv=fmaf(v,v,qv); }
        #pragma unroll
        for (int d=16; d>0; d>>=1){
            sv += __shfl_down_sync(0xffffffffu, sv, d);
            qv += __shfl_down_sync(0xffffffffu, qv, d);
        }
        if (tx == 0){ red[o*8+ty]=sv; red[128+o*8+ty]=qv; }
    }
    __syncthreads();
    if (tid < 16){
        float S=0.f, Q=0.f;
        #pragma unroll
        for (int w=0;w<8;w++){ S+=red[tid*8+w]; Q+=red[128+tid*8+w]; }
        int p = n*256 + blockIdx.y*gridDim.x + blockIdx.x;  // < 512
        g_part[((oc0+tid)*512+p)*2+0] = S;
        g_part[((oc0+tid)*512+p)*2+1] = Q;
    }
}

// ---------------- reduce conv32 partials (512/channel) -> scale1/shift1 --------
__global__ __launch_bounds__(256) void stats2_k(const float* __restrict__ g,
                                                const float* __restrict__ b)
{
    const int c = blockIdx.x;
    __shared__ float ss[256], qq[256];
    ss[threadIdx.x] = g_part[(c*512+threadIdx.x)*2+0] + g_part[(c*512+threadIdx.x+256)*2+0];
    qq[threadIdx.x] = g_part[(c*512+threadIdx.x)*2+1] + g_part[(c*512+threadIdx.x+256)*2+1];
    __syncthreads();
    for (int o=128;o>0;o>>=1){
        if (threadIdx.x < o){ ss[threadIdx.x]+=ss[threadIdx.x+o]; qq[threadIdx.x]+=qq[threadIdx.x+o]; }
        __syncthreads();
    }
    if (threadIdx.x==0){
        float mean = ss[0]/(float)NHW;
        float var  = qq[0]/(float)NHW - mean*mean;
        float sc = g[c]*rsqrtf(var + 1e-5f);
        g_scale1[c]=sc; g_shift1[c]=b[c]-mean*sc;
    }
}

// ---------------- z = sum_c relu(bn(auxb1_c)) * b2w_c, float4 (4 px/thread) ----
__global__ __launch_bounds__(256) void b2_k(const float* __restrict__ w2)
{
    __shared__ float s[32], h[32], ww[32];
    if (threadIdx.x < 32){ s[threadIdx.x]=g_scale1[threadIdx.x];
                           h[threadIdx.x]=g_shift1[threadIdx.x];
                           ww[threadIdx.x]=w2[threadIdx.x]; }
    __syncthreads();
    int base = (blockIdx.x*256 + threadIdx.x)*4;
    int n = base / HWSZ, r = base - n*HWSZ;
    float4 acc = make_float4(0.f,0.f,0.f,0.f);
    #pragma unroll
    for (int c=0;c<32;c++){
        float4 v = *(const float4*)&g_auxb1[((size_t)(n*32+c))*HWSZ + r];
        float sc = s[c], hc = h[c], wc = ww[c];
        acc.x = fmaf(fmaxf(fmaf(v.x,sc,hc),0.f), wc, acc.x);
        acc.y = fmaf(fmaxf(fmaf(v.y,sc,hc),0.f), wc, acc.y);
        acc.z = fmaf(fmaxf(fmaf(v.z,sc,hc),0.f), wc, acc.z);
        acc.w = fmaf(fmaxf(fmaf(v.w,sc,hc),0.f), wc, acc.w);
    }
    *(float4*)&g_z[base] = acc;
    float sv = acc.x + acc.y + acc.z + acc.w;
    float qv = fmaf(acc.x,acc.x, fmaf(acc.y,acc.y, fmaf(acc.z,acc.z, acc.w*acc.w)));
    __shared__ float ss[256], qq[256];
    ss[threadIdx.x]=sv; qq[threadIdx.x]=qv;
    __syncthreads();
    for (int o=128;o>0;o>>=1){
        if (threadIdx.x < o){ ss[threadIdx.x]+=ss[threadIdx.x+o]; qq[threadIdx.x]+=qq[threadIdx.x+o]; }
        __syncthreads();
    }
    if (threadIdx.x==0){
        g_part[blockIdx.x*2+0]=ss[0];
        g_part[blockIdx.x*2+1]=qq[0];
    }
}

// ---------------- x1 = conv(feat, w_out) ; inp = x1 + relu(bn(z)) --------------
// folded z-BN stats; 2px x 2rows per thread, float2 smem reads; tile 64x16
__global__ __launch_bounds__(256) void wout_inp_k(
    const float* __restrict__ feat, const float* __restrict__ wt,
    const float* __restrict__ b2g, const float* __restrict__ b2b)
{
    __shared__ float tile[2][18][68];
    __shared__ float wsm[32*9];
    __shared__ float rs[256], rq[256];
    const int tid = threadIdx.y*32 + threadIdx.x;
    const int tx = threadIdx.x, ty = threadIdx.y;
    const int n = blockIdx.z;
    const int x0 = blockIdx.x*64, y0 = blockIdx.y*16;
    const int TSZ = 18*66;
    const int NLD = 5;

    {
        float s = g_part[tid*2+0] + g_part[(tid+256)*2+0];
        float q = g_part[tid*2+1] + g_part[(tid+256)*2+1];
        rs[tid]=s; rq[tid]=q;
        __syncthreads();
        for (int o=128;o>0;o>>=1){
            if (tid < o){ rs[tid]+=rs[tid+o]; rq[tid]+=rq[tid+o]; }
            __syncthreads();
        }
        if (tid==0){
            float mean = rs[0]/(float)NHW;
            float var  = rq[0]/(float)NHW - mean*mean;
            float sc = b2g[0]*rsqrtf(var + 1e-5f);
            rs[0]=sc; rq[0]=b2b[0]-mean*sc;
        }
        __syncthreads();
    }
    const float s2 = rs[0], h2 = rq[0];

    for (int i = tid; i < 288; i += 256) wsm[i] = wt[i];

    int off[NLD]; unsigned vmask = 0u;
    #pragma unroll
    for (int j=0;j<NLD;j++){
        int i = tid + j*256;
        int yy = i/66, xx = i - yy*66;
        int gy = y0+yy-1, gx = x0+xx-1;
        bool v = (i < TSZ) && ((unsigned)gy < HH) && ((unsigned)gx < WW);
        off[j] = v ? (gy*WW + gx) : 0;
        if (v) vmask |= (1u<<j);
    }
    {
        const float* src = feat + (size_t)(n*32)*HWSZ;
        float rld[NLD];
        #pragma unroll
        for (int j=0;j<NLD;j++) rld[j] = ((vmask>>j)&1u) ? src[off[j]] : 0.f;
        float* tb = &tile[0][0][0];
        #pragma unroll
        for (int j=0;j<NLD;j++){
            int i = tid + j*256;
            if (i < TSZ){ int yy=i/66, xx=i-yy*66; tb[yy*68+xx] = rld[j]; }
        }
    }
    __syncthreads();

    float acc[2][2];
    acc[0][0]=acc[0][1]=acc[1][0]=acc[1][1]=0.f;

    for (int c = 0; c < 32; c++){
        const int cur = c & 1;
        float rld[NLD];
        if (c+1 < 32){
            const float* src = feat + (size_t)(n*32 + c+1)*HWSZ;
            #pragma unroll
            for (int j=0;j<NLD;j++) rld[j] = ((vmask>>j)&1u) ? src[off[j]] : 0.f;
        }
        #pragma unroll
        for (int r=0;r<3;r++){
            float w0 = wsm[c*9 + r*3 + 0];
            float w1 = wsm[c*9 + r*3 + 1];
            float w2 = wsm[c*9 + r*3 + 2];
            #pragma unroll
            for (int k=0;k<2;k++){
                const int row = ty + 8*k + r;
                float2 A = *(const float2*)&tile[cur][row][2*tx];
                float2 B = *(const float2*)&tile[cur][row][2*tx+2];
                acc[k][0] = fmaf(w0, A.x, acc[k][0]);
                acc[k][0] = fmaf(w1, A.y, acc[k][0]);
                acc[k][0] = fmaf(w2, B.x, acc[k][0]);
                acc[k][1] = fmaf(w0, A.y, acc[k][1]);
                acc[k][1] = fmaf(w1, B.x, acc[k][1]);
                acc[k][1] = fmaf(w2, B.y, acc[k][1]);
            }
        }
        if (c+1 < 32){
            float* tb = &tile[cur^1][0][0];
            #pragma unroll
            for (int j=0;j<NLD;j++){
                int i = tid + j*256;
                if (i < TSZ){ int yy=i/66, xx=i-yy*66; tb[yy*68+xx] = rld[j]; }
            }
        }
        __syncthreads();
    }

    #pragma unroll
    for (int k=0;k<2;k++){
        int idx = (y0+ty+8*k)*WW + x0 + 2*tx;
        float2 zz = *(const float2*)&g_z[(size_t)n*HWSZ + idx];
        float2 o;
        o.x = acc[k][0] + fmaxf(zz.x*s2 + h2, 0.f);
        o.y = acc[k][1] + fmaxf(zz.y*s2 + h2, 0.f);
        *(float2*)&g_inp[(size_t)n*HWSZ + idx] = o;
    }
}

// ---------------- xm25 = aff5(inp) + conv(xm9(inp), d1), xm9 fused -------------
__global__ __launch_bounds__(256) void xm25f_k(const float* __restrict__ d0,
                                               const float* __restrict__ d1)
{
    __shared__ float ti[12][68];
    __shared__ float t9[10][68];
    __shared__ float w0sm[81];
    __shared__ float w1sm[25*81];
    const int n = blockIdx.z;
    const int x0 = blockIdx.x*64, y0 = blockIdx.y*8;
    const int tid = threadIdx.y*32 + threadIdx.x;
    const int tx = threadIdx.x, ty = threadIdx.y;

    if (tid < 81) w0sm[tid] = d0[tid];
    for (int i=tid;i<25*81;i+=256) w1sm[i] = d1[i];
    for (int i=tid;i<12*68;i+=256){
        int yy=i/68, xx=i-yy*68;
        int gy=y0+yy-2, gx=x0+xx-2;
        ti[yy][xx] = ((unsigned)gy<HH && (unsigned)gx<WW) ? g_inp[(size_t)n*HWSZ + (size_t)gy*WW + gx] : 0.f;
    }
    __syncthreads();

    float acc[25][2];
    #pragma unroll
    for (int t=0;t<25;t++){ acc[t][0]=0.f; acc[t][1]=0.f; }

    for (int c=0;c<9;c++){
        const int ii = c/3, jj = c%3;
        float w0[9];
        #pragma unroll
        for (int u=0;u<9;u++) w0[u] = w0sm[c*9+u];
        for (int i=tid;i<10*66;i+=256){
            int yy=i/66, xx=i-yy*66;
            int gy=y0+yy-1, gx=x0+xx-1;
            float val = 0.f;
            if ((unsigned)gy<HH && (unsigned)gx<WW){
                float ctr = ti[yy+1][xx+1];
                val = ti[yy+ii][xx+jj]*ctr;
                #pragma unroll
                for (int r=0;r<3;r++)
                #pragma unroll
                for (int s=0;s<3;s++)
                    val = fmaf(ti[yy+r][xx+s], w0[r*3+s], val);
            }
            t9[yy][xx] = val;
        }
        __syncthreads();

        #pragma unroll
        for (int r=0;r<3;r++)
        #pragma unroll
        for (int s=0;s<3;s++){
            float v0 = t9[ty + r][tx + s];
            float v1 = t9[ty + r][tx + 32 + s];
            #pragma unroll
            for (int t=0;t<25;t++){
                float wv = w1sm[t*81 + c*9 + r*3 + s];
                acc[t][0] = fmaf(wv, v0, acc[t][0]);
                acc[t][1] = fmaf(wv, v1, acc[t][1]);
            }
        }
        __syncthreads();
    }

    #pragma unroll
    for (int t=0;t<25;t++){
        const int ai = t/5, aj = t%5;
        #pragma unroll
        for (int k=0;k<2;k++){
            int lx = tx + 32*k;
            float ctr = ti[ty+2][lx+2];
            float aff = ti[ty+ai][lx+aj] * ctr;
            g_xm25[((size_t)(n*25+t))*HWSZ + (size_t)(y0+ty)*WW + x0 + lx] = aff + acc[t][k];
        }
    }
}

// ---------------- conv4d + affinity reduce + seg output ------------------------
__global__ __launch_bounds__(256) void final_k(const float* __restrict__ d4,
                                               float* __restrict__ segout)
{
    __shared__ float t25[25][10][34];
    __shared__ float ti[12][36];
    __shared__ float wsm[81];
    const int n = blockIdx.z;
    const int x0 = blockIdx.x*32, y0 = blockIdx.y*8;
    const int tid = threadIdx.y*32 + threadIdx.x;
    if (tid < 81) wsm[tid] = d4[tid];
    for (int i = tid; i < 25*340; i += 256){
        int c = i/340, rr = i - c*340, yy = rr/34, xx = rr%34;
        int gy=y0+yy-1, gx=x0+xx-1;
        t25[c][yy][xx] = ((unsigned)gy<HH && (unsigned)gx<WW) ? g_xm25[((size_t)(n*25+c))*HWSZ + gy*WW + gx] : 0.f;
    }
    for (int i=tid;i<432;i+=256){
        int yy=i/36, xx=i%36;
        int gy=y0+yy-2, gx=x0+xx-2;
        ti[yy][xx] = ((unsigned)gy<HH && (unsigned)gx<WW) ? g_inp[(size_t)n*HWSZ + gy*WW + gx] : 0.f;
    }
    __syncthreads();

    float kacc[25];
    #pragma unroll
    for (int t=0;t<25;t++) kacc[t]=0.f;

    #pragma unroll
    for (int r=0;r<3;r++)
    #pragma unroll
    for (int s=0;s<3;s++){
        float wv[9];
        #pragma unroll
        for (int p=0;p<3;p++)
        #pragma unroll
        for (int q=0;q<3;q++) wv[p*3+q] = wsm[((p*3+q)*3+r)*3 + s];
        float L[25];
        #pragma unroll
        for (int u=0;u<5;u++)
        #pragma unroll
        for (int v=0;v<5;v++) L[u*5+v] = t25[u*5+v][threadIdx.y+r][threadIdx.x+s];
        #pragma unroll
        for (int d=0;d<5;d++)
        #pragma unroll
        for (int e=0;e<5;e++)
        #pragma unroll
        for (int p=0;p<3;p++){
            int u = d-1+p; if (u < 0 || u > 4) continue;
            #pragma unroll
            for (int q=0;q<3;q++){
                int v = e-1+q; if (v < 0 || v > 4) continue;
                kacc[d*5+e] = fmaf(L[u*5+v], wv[p*3+q], kacc[d*5+e]);
            }
        }
    }
    float sum = 0.f;
    #pragma unroll
    for (int ii=0;ii<5;ii++)
    #pragma unroll
    for (int jj=0;jj<5;jj++)
        sum = fmaf(ti[threadIdx.y+ii][threadIdx.x+jj], kacc[ii*5+jj], sum);

    float o = sum / 25.0f;
    int idx = (y0+threadIdx.y)*WW + x0 + threadIdx.x;
    segout[((size_t)(n*2+0))*HWSZ + idx] = 1.0f - o;
    segout[((size_t)(n*2+1))*HWSZ + idx] = o;
}

// ---------------- top-k threshold: radix select on float keys ------------------
__device__ __forceinline__ unsigned f2key(float f){
    unsigned u = __float_as_uint(f);
    return (u & 0x80000000u) ? ~u : (u | 0x80000000u);
}
__device__ __forceinline__ float key2f(unsigned k){
    unsigned u = (k & 0x80000000u) ? (k & 0x7fffffffu) : ~k;
    return __uint_as_float(u);
}

__global__ __launch_bounds__(256) void hist_k(const float* __restrict__ seg, int shift)
{
    __shared__ unsigned hh[256];
    const int j = blockIdx.y;
    hh[threadIdx.x]=0u;
    __syncthreads();
    const bool first = (shift == 24);
    unsigned pfx = first ? 0u : g_prefix[j];
    unsigned mask = first ? 0u : (0xFFFFFFFFu << (shift+8));
    const float4* p = (const float4*)(seg + (size_t)j*HWSZ);
    for (int i = blockIdx.x*256 + threadIdx.x; i < HWSZ/4; i += 64*256){
        float4 v = p[i];
        unsigned k0 = f2key(v.x), k1 = f2key(v.y), k2 = f2key(v.z), k3 = f2key(v.w);
        if (first || (k0 & mask) == pfx) atomicAdd(&hh[(k0>>shift)&255u], 1u);
        if (first || (k1 & mask) == pfx) atomicAdd(&hh[(k1>>shift)&255u], 1u);
        if (first || (k2 & mask) == pfx) atomicAdd(&hh[(k2>>shift)&255u], 1u);
        if (first || (k3 & mask) == pfx) atomicAdd(&hh[(k3>>shift)&255u], 1u);
    }
    __syncthreads();
    if (hh[threadIdx.x]) atomicAdd(&g_hist[j][threadIdx.x], hh[threadIdx.x]);
}

__global__ void select_k(const float* __restrict__ ratio, int shift,
                         int first, int last)
{
    int j = threadIdx.x;
    if (j >= 4) return;
    int rem; unsigned pfx;
    if (first){
        int n = j >> 1;
        float fp = floorf(ratio[n]*(float)HWSZ);
        int k = (int)floorf(fp*0.1f);
        rem = k-1; if (rem < 0) rem = 0;
        pfx = 0u;
    } else {
        rem = g_remain[j]; pfx = g_prefix[j];
    }
    int done = 0;
    for (int b=255;b>=0;b--){
        unsigned c = g_hist[j][b];
        if (!done){
            if ((int)c > rem){ pfx |= ((unsigned)b)<<shift; done=1; }
            else rem -= (int)c;
        }
        g_hist[j][b]=0u;
    }
    g_prefix[j]=pfx; g_remain[j]=rem;
    if (last) g_thr[j] = key2f(pfx);
}

// ---------------- host orchestration -------------------------------------------
struct Ptrs { float *feat, *aux, *auxb1; };

template<bool ERASE>
static void run_pipeline(const float* img, const float* seg, float* seg_out,
                         const float* w1, const float* wa, const float* wout,
                         const float* b1w, const float* b1g, const float* b1b,
                         const float* b2w, const float* b2g, const float* b2b,
                         const float* d0w, const float* d1w, const float* d4w,
                         const Ptrs& P)
{
    dim3 blk(32,8);
    dualconv3_k<ERASE><<<dim3(16,16,NB*4), blk>>>(img, seg, w1, wa, P.feat, P.aux);
    conv32_k<<<dim3(16,16,NB*2), blk>>>(P.aux, b1w, P.auxb1);
    stats2_k<<<32,256>>>(b1g, b1b);
    b2_k<<<NHW/1024, 256>>>(b2w);
    wout_inp_k<<<dim3(8,32,NB), blk>>>(P.feat, wout, b2g, b2b);
    xm25f_k<<<dim3(8,64,NB), blk>>>(d0w, d1w);
    final_k<<<dim3(16,64,NB), blk>>>(d4w, seg_out);
}

extern "C" void kernel_launch(void* const* d_in, const int* in_sizes, int n_in,
                              void* d_out, int out_size)
{
    const float* x     = (const float*)d_in[0];
    const float* ratio = (const float*)d_in[1];
    const float* w1    = (const float*)d_in[2];
    const float* wa    = (const float*)d_in[3];
    const float* wout  = (const float*)d_in[4];
    const float* b1w   = (const float*)d_in[5];
    const float* b1g   = (const float*)d_in[6];
    const float* b1b   = (const float*)d_in[7];
    const float* b2w   = (const float*)d_in[8];
    const float* b2g   = (const float*)d_in[9];
    const float* b2b   = (const float*)d_in[10];
    const float* d0w   = (const float*)d_in[11];
    const float* d1w   = (const float*)d_in[12];
    const float* d4w   = (const float*)d_in[13];
    float* out = (float*)d_out;

    Ptrs P;
    void* p;
    cudaGetSymbolAddress(&p, g_feat);   P.feat   = (float*)p;
    cudaGetSymbolAddress(&p, g_aux);    P.aux    = (float*)p;
    cudaGetSymbolAddress(&p, g_auxb1);  P.auxb1  = (float*)p;

    // pipeline 1 -> x1 (first half of output)
    run_pipeline<false>(x, nullptr, out, w1, wa, wout, b1w, b1g, b1b,
                        b2w, b2g, b2b, d0w, d1w, d4w, P);

    // erasing threshold: per-(n,c) radix select
    for (int pass=0; pass<4; ++pass){
        int shift = 24 - 8*pass;
        hist_k<<<dim3(64,4), 256>>>(out, shift);
        select_k<<<1,4>>>(ratio, shift, pass==0 ? 1 : 0, pass==3 ? 1 : 0);
    }

    // pipeline 2 (erase fused into its dual conv3) -> x2 (second half)
    run_pipeline<true>(x, out, out + (size_t)NB*2*HWSZ, w1, wa, wout,
                       b1w, b1g, b1b, b2w, b2g, b2b, d0w, d1w, d4w, P);
}

// round 14
// speedup vs baseline: 1.9075x; 1.9075x over previous
#include <cuda_runtime.h>
#include <math.h>

#define HH 512
#define WW 512
#define NB 2
#define HWSZ (HH*WW)          // 262144
#define NHW (NB*HWSZ)         // 524288

// ---------------- scratch (device globals; no allocation allowed) -------------
__device__ float g_feat [NB*32*HWSZ];
__device__ float g_aux  [NB*32*HWSZ];
__device__ float g_auxb1[NB*32*HWSZ];
__device__ float g_z    [NHW];
__device__ float g_inp  [NHW];
__device__ float g_xm25 [NB*25*HWSZ];
__device__ float g_part [32*512*2];
__device__ float g_scale1[32], g_shift1[32];
__device__ unsigned g_hist[4][256];
__device__ unsigned g_prefix[4];
__device__ int      g_remain[4];
__device__ float    g_thr[4];

// ---------------- fused dual 3x3 conv (3->32 twice): 16 oc x 4 rows/thread ----
template<bool ERASE>
__global__ __launch_bounds__(256) void dualconv3_k(
    const float* __restrict__ img, const float* __restrict__ seg,
    const float* __restrict__ w1, const float* __restrict__ wa,
    float* __restrict__ feat, float* __restrict__ aux)
{
    __shared__ float tile[2][34][34];
    __shared__ float wsm[16*27];
    const int tid = threadIdx.y*32 + threadIdx.x;
    const int tx = threadIdx.x, ty = threadIdx.y;
    const int grp = blockIdx.z & 3;
    const int n   = blockIdx.z >> 2;
    const int oc0 = grp*8;
    const int x0 = blockIdx.x*32, y0 = blockIdx.y*32;
    const int TSZ = 34*34;
    const int NLD = 5;

    for (int i = tid; i < 16*27; i += 256){
        int o = i/27, rr = i - o*27;
        wsm[i] = (o < 8) ? w1[(oc0+o)*27 + rr] : wa[(oc0+o-8)*27 + rr];
    }

    int off[NLD]; unsigned vmask = 0u, emask = 0u;
    #pragma unroll
    for (int j=0;j<NLD;j++){
        int i = tid + j*256;
        int yy = i/34, xx = i - yy*34;
        int gy = y0+yy-1, gx = x0+xx-1;
        bool v = (i < TSZ) && ((unsigned)gy < HH) && ((unsigned)gx < WW);
        off[j] = v ? (gy*WW + gx) : 0;
        if (v) vmask |= (1u<<j);
    }
    if (ERASE){
        float t0 = g_thr[n*2+0], t1 = g_thr[n*2+1];
        #pragma unroll
        for (int j=0;j<NLD;j++){
            if ((vmask>>j)&1u){
                float s0 = seg[((size_t)(n*2+0))*HWSZ + off[j]];
                float s1 = seg[((size_t)(n*2+1))*HWSZ + off[j]];
                if (s0 > t0 || s1 > t1) emask |= (1u<<j);
            }
        }
    }

    {
        const float* src = img + (size_t)(n*3)*HWSZ;
        float rld[NLD];
        #pragma unroll
        for (int j=0;j<NLD;j++)
            rld[j] = (((vmask>>j)&1u) && !((emask>>j)&1u)) ? src[off[j]] : 0.f;
        float* tb = &tile[0][0][0];
        #pragma unroll
        for (int j=0;j<NLD;j++){ int i = tid + j*256; if (i < TSZ) tb[i] = rld[j]; }
    }
    __syncthreads();

    float acc[16][4];
    #pragma unroll
    for (int o=0;o<16;o++)
        #pragma unroll
        for (int k=0;k<4;k++) acc[o][k]=0.f;

    for (int c = 0; c < 3; c++){
        const int cur = c & 1;
        float rld[NLD];
        if (c+1 < 3){
            const float* src = img + (size_t)(n*3 + c+1)*HWSZ;
            #pragma unroll
            for (int j=0;j<NLD;j++)
                rld[j] = (((vmask>>j)&1u) && !((emask>>j)&1u)) ? src[off[j]] : 0.f;
        }
        #pragma unroll
        for (int r=0;r<3;r++)
        #pragma unroll
        for (int s=0;s<3;s++){
            float wv[16];
            #pragma unroll
            for (int o=0;o<16;o++) wv[o] = wsm[o*27 + c*9 + r*3 + s];
            #pragma unroll
            for (int k=0;k<4;k++){
                float v = tile[cur][ty + 8*k + r][tx + s];
                #pragma unroll
                for (int o=0;o<16;o++) acc[o][k] = fmaf(wv[o], v, acc[o][k]);
            }
        }
        if (c+1 < 3){
            float* tb = &tile[cur^1][0][0];
            #pragma unroll
            for (int j=0;j<NLD;j++){ int i = tid + j*256; if (i < TSZ) tb[i] = rld[j]; }
        }
        __syncthreads();
    }

    #pragma unroll
    for (int o=0;o<16;o++)
    #pragma unroll
    for (int k=0;k<4;k++){
        float v = fmaxf(acc[o][k], 0.f);
        size_t idx = (size_t)(y0+ty+8*k)*WW + x0 + tx;
        if (o < 8) feat[((size_t)(n*32 + oc0 + o  ))*HWSZ + idx] = v;
        else       aux [((size_t)(n*32 + oc0 + o-8))*HWSZ + idx] = v;
    }
}

// ---------------- 32->32 3x3 conv: 16 oc x 4 rows/thread, fused BN partials ----
// tile 32x32; 2 oc-groups; 2 blocks/SM (R12 proven form)
__global__ __launch_bounds__(256,2) void conv32_k(
    const float* __restrict__ in, const float* __restrict__ wt,
    float* __restrict__ out)
{
    __shared__ float tile[2][34][34];
    __shared__ float wsm[16*32*9];
    const int tid = threadIdx.y*32 + threadIdx.x;
    const int tx = threadIdx.x, ty = threadIdx.y;
    const int grp = blockIdx.z & 1;
    const int n   = blockIdx.z >> 1;
    const int oc0 = grp*16;
    const int x0 = blockIdx.x*32, y0 = blockIdx.y*32;
    const int TSZ = 34*34;
    const int NLD = 5;

    for (int i = tid; i < 16*32*9; i += 256) wsm[i] = wt[oc0*32*9 + i];

    int off[NLD]; unsigned vmask = 0u;
    #pragma unroll
    for (int j=0;j<NLD;j++){
        int i = tid + j*256;
        int yy = i/34, xx = i - yy*34;
        int gy = y0+yy-1, gx = x0+xx-1;
        bool v = (i < TSZ) && ((unsigned)gy < HH) && ((unsigned)gx < WW);
        off[j] = v ? (gy*WW + gx) : 0;
        if (v) vmask |= (1u<<j);
    }

    {
        const float* src = in + (size_t)(n*32)*HWSZ;
        float rld[NLD];
        #pragma unroll
        for (int j=0;j<NLD;j++) rld[j] = ((vmask>>j)&1u) ? src[off[j]] : 0.f;
        float* tb = &tile[0][0][0];
        #pragma unroll
        for (int j=0;j<NLD;j++){ int i = tid + j*256; if (i < TSZ) tb[i] = rld[j]; }
    }
    __syncthreads();

    float acc[16][4];
    #pragma unroll
    for (int o=0;o<16;o++)
        #pragma unroll
        for (int k=0;k<4;k++) acc[o][k]=0.f;

    for (int c = 0; c < 32; c++){
        const int cur = c & 1;
        float rld[NLD];
        if (c+1 < 32){
            const float* src = in + (size_t)(n*32 + c+1)*HWSZ;
            #pragma unroll
            for (int j=0;j<NLD;j++) rld[j] = ((vmask>>j)&1u) ? src[off[j]] : 0.f;
        }
        #pragma unroll
        for (int r=0;r<3;r++)
        #pragma unroll
        for (int s=0;s<3;s++){
            float wv[16];
            #pragma unroll
            for (int o=0;o<16;o++) wv[o] = wsm[(o*32+c)*9 + r*3 + s];
            #pragma unroll
            for (int k=0;k<4;k++){
                float v = tile[cur][ty + 8*k + r][tx + s];
                #pragma unroll
                for (int o=0;o<16;o++) acc[o][k] = fmaf(wv[o], v, acc[o][k]);
            }
        }
        if (c+1 < 32){
            float* tb = &tile[cur^1][0][0];
            #pragma unroll
            for (int j=0;j<NLD;j++){ int i = tid + j*256; if (i < TSZ) tb[i] = rld[j]; }
        }
        __syncthreads();
    }

    #pragma unroll
    for (int o=0;o<16;o++)
    #pragma unroll
    for (int k=0;k<4;k++)
        out[((size_t)(n*32 + oc0 + o))*HWSZ + (size_t)(y0+ty+8*k)*WW + x0 + tx] = acc[o][k];

    // deterministic per-block BN partials (one oc at a time: no reg blowup)
    float* red = &tile[0][0][0];
    #pragma unroll
    for (int o=0;o<16;o++){
        float sv=0.f, qv=0.f;
        #pragma unroll
        for (int k=0;k<4;k++){ float v=acc[o][k]; sv+=v; qv=fmaf(v,v,qv); }
        #pragma unroll
        for (int d=16; d>0; d>>=1){
            sv += __shfl_down_sync(0xffffffffu, sv, d);
            qv += __shfl_down_sync(0xffffffffu, qv, d);
        }
        if (tx == 0){ red[o*8+ty]=sv; red[128+o*8+ty]=qv; }
    }
    __syncthreads();
    if (tid < 16){
        float S=0.f, Q=0.f;
        #pragma unroll
        for (int w=0;w<8;w++){ S+=red[tid*8+w]; Q+=red[128+tid*8+w]; }
        int p = n*256 + blockIdx.y*gridDim.x + blockIdx.x;  // < 512
        g_part[((oc0+tid)*512+p)*2+0] = S;
        g_part[((oc0+tid)*512+p)*2+1] = Q;
    }
}

// ---------------- reduce conv32 partials (512/channel) -> scale1/shift1 --------
__global__ __launch_bounds__(256) void stats2_k(const float* __restrict__ g,
                                                const float* __restrict__ b)
{
    const int c = blockIdx.x;
    __shared__ float ss[256], qq[256];
    ss[threadIdx.x] = g_part[(c*512+threadIdx.x)*2+0] + g_part[(c*512+threadIdx.x+256)*2+0];
    qq[threadIdx.x] = g_part[(c*512+threadIdx.x)*2+1] + g_part[(c*512+threadIdx.x+256)*2+1];
    __syncthreads();
    for (int o=128;o>0;o>>=1){
        if (threadIdx.x < o){ ss[threadIdx.x]+=ss[threadIdx.x+o]; qq[threadIdx.x]+=qq[threadIdx.x+o]; }
        __syncthreads();
    }
    if (threadIdx.x==0){
        float mean = ss[0]/(float)NHW;
        float var  = qq[0]/(float)NHW - mean*mean;
        float sc = g[c]*rsqrtf(var + 1e-5f);
        g_scale1[c]=sc; g_shift1[c]=b[c]-mean*sc;
    }
}

// ---------------- z = sum_c relu(bn(auxb1_c)) * b2w_c, float4 (4 px/thread) ----
__global__ __launch_bounds__(256) void b2_k(const float* __restrict__ w2)
{
    __shared__ float s[32], h[32], ww[32];
    if (threadIdx.x < 32){ s[threadIdx.x]=g_scale1[threadIdx.x];
                           h[threadIdx.x]=g_shift1[threadIdx.x];
                           ww[threadIdx.x]=w2[threadIdx.x]; }
    __syncthreads();
    int base = (blockIdx.x*256 + threadIdx.x)*4;
    int n = base / HWSZ, r = base - n*HWSZ;
    float4 acc = make_float4(0.f,0.f,0.f,0.f);
    #pragma unroll
    for (int c=0;c<32;c++){
        float4 v = *(const float4*)&g_auxb1[((size_t)(n*32+c))*HWSZ + r];
        float sc = s[c], hc = h[c], wc = ww[c];
        acc.x = fmaf(fmaxf(fmaf(v.x,sc,hc),0.f), wc, acc.x);
        acc.y = fmaf(fmaxf(fmaf(v.y,sc,hc),0.f), wc, acc.y);
        acc.z = fmaf(fmaxf(fmaf(v.z,sc,hc),0.f), wc, acc.z);
        acc.w = fmaf(fmaxf(fmaf(v.w,sc,hc),0.f), wc, acc.w);
    }
    *(float4*)&g_z[base] = acc;
    float sv = acc.x + acc.y + acc.z + acc.w;
    float qv = fmaf(acc.x,acc.x, fmaf(acc.y,acc.y, fmaf(acc.z,acc.z, acc.w*acc.w)));
    __shared__ float ss[256], qq[256];
    ss[threadIdx.x]=sv; qq[threadIdx.x]=qv;
    __syncthreads();
    for (int o=128;o>0;o>>=1){
        if (threadIdx.x < o){ ss[threadIdx.x]+=ss[threadIdx.x+o]; qq[threadIdx.x]+=qq[threadIdx.x+o]; }
        __syncthreads();
    }
    if (threadIdx.x==0){
        g_part[blockIdx.x*2+0]=ss[0];
        g_part[blockIdx.x*2+1]=qq[0];
    }
}

// ---------------- x1 = conv(feat, w_out) ; inp = x1 + relu(bn(z)) --------------
// folded z-BN stats; 2px x 2rows per thread, float2 smem reads; tile 64x16
__global__ __launch_bounds__(256) void wout_inp_k(
    const float* __restrict__ feat, const float* __restrict__ wt,
    const float* __restrict__ b2g, const float* __restrict__ b2b)
{
    __shared__ float tile[2][18][68];
    __shared__ float wsm[32*9];
    __shared__ float rs[256], rq[256];
    const int tid = threadIdx.y*32 + threadIdx.x;
    const int tx = threadIdx.x, ty = threadIdx.y;
    const int n = blockIdx.z;
    const int x0 = blockIdx.x*64, y0 = blockIdx.y*16;
    const int TSZ = 18*66;
    const int NLD = 5;

    {
        float s = g_part[tid*2+0] + g_part[(tid+256)*2+0];
        float q = g_part[tid*2+1] + g_part[(tid+256)*2+1];
        rs[tid]=s; rq[tid]=q;
        __syncthreads();
        for (int o=128;o>0;o>>=1){
            if (tid < o){ rs[tid]+=rs[tid+o]; rq[tid]+=rq[tid+o]; }
            __syncthreads();
        }
        if (tid==0){
            float mean = rs[0]/(float)NHW;
            float var  = rq[0]/(float)NHW - mean*mean;
            float sc = b2g[0]*rsqrtf(var + 1e-5f);
            rs[0]=sc; rq[0]=b2b[0]-mean*sc;
        }
        __syncthreads();
    }
    const float s2 = rs[0], h2 = rq[0];

    for (int i = tid; i < 288; i += 256) wsm[i] = wt[i];

    int off[NLD]; unsigned vmask = 0u;
    #pragma unroll
    for (int j=0;j<NLD;j++){
        int i = tid + j*256;
        int yy = i/66, xx = i - yy*66;
        int gy = y0+yy-1, gx = x0+xx-1;
        bool v = (i < TSZ) && ((unsigned)gy < HH) && ((unsigned)gx < WW);
        off[j] = v ? (gy*WW + gx) : 0;
        if (v) vmask |= (1u<<j);
    }
    {
        const float* src = feat + (size_t)(n*32)*HWSZ;
        float rld[NLD];
        #pragma unroll
        for (int j=0;j<NLD;j++) rld[j] = ((vmask>>j)&1u) ? src[off[j]] : 0.f;
        float* tb = &tile[0][0][0];
        #pragma unroll
        for (int j=0;j<NLD;j++){
            int i = tid + j*256;
            if (i < TSZ){ int yy=i/66, xx=i-yy*66; tb[yy*68+xx] = rld[j]; }
        }
    }
    __syncthreads();

    float acc[2][2];
    acc[0][0]=acc[0][1]=acc[1][0]=acc[1][1]=0.f;

    for (int c = 0; c < 32; c++){
        const int cur = c & 1;
        float rld[NLD];
        if (c+1 < 32){
            const float* src = feat + (size_t)(n*32 + c+1)*HWSZ;
            #pragma unroll
            for (int j=0;j<NLD;j++) rld[j] = ((vmask>>j)&1u) ? src[off[j]] : 0.f;
        }
        #pragma unroll
        for (int r=0;r<3;r++){
            float w0 = wsm[c*9 + r*3 + 0];
            float w1 = wsm[c*9 + r*3 + 1];
            float w2 = wsm[c*9 + r*3 + 2];
            #pragma unroll
            for (int k=0;k<2;k++){
                const int row = ty + 8*k + r;
                float2 A = *(const float2*)&tile[cur][row][2*tx];
                float2 B = *(const float2*)&tile[cur][row][2*tx+2];
                acc[k][0] = fmaf(w0, A.x, acc[k][0]);
                acc[k][0] = fmaf(w1, A.y, acc[k][0]);
                acc[k][0] = fmaf(w2, B.x, acc[k][0]);
                acc[k][1] = fmaf(w0, A.y, acc[k][1]);
                acc[k][1] = fmaf(w1, B.x, acc[k][1]);
                acc[k][1] = fmaf(w2, B.y, acc[k][1]);
            }
        }
        if (c+1 < 32){
            float* tb = &tile[cur^1][0][0];
            #pragma unroll
            for (int j=0;j<NLD;j++){
                int i = tid + j*256;
                if (i < TSZ){ int yy=i/66, xx=i-yy*66; tb[yy*68+xx] = rld[j]; }
            }
        }
        __syncthreads();
    }

    #pragma unroll
    for (int k=0;k<2;k++){
        int idx = (y0+ty+8*k)*WW + x0 + 2*tx;
        float2 zz = *(const float2*)&g_z[(size_t)n*HWSZ + idx];
        float2 o;
        o.x = acc[k][0] + fmaxf(zz.x*s2 + h2, 0.f);
        o.y = acc[k][1] + fmaxf(zz.y*s2 + h2, 0.f);
        *(float2*)&g_inp[(size_t)n*HWSZ + idx] = o;
    }
}

// ---------------- xm25 = aff5(inp) + conv(xm9(inp), d1), xm9 fused -------------
__global__ __launch_bounds__(256) void xm25f_k(const float* __restrict__ d0,
                                               const float* __restrict__ d1)
{
    __shared__ float ti[12][68];
    __shared__ float t9[10][68];
    __shared__ float w0sm[81];
    __shared__ float w1sm[25*81];
    const int n = blockIdx.z;
    const int x0 = blockIdx.x*64, y0 = blockIdx.y*8;
    const int tid = threadIdx.y*32 + threadIdx.x;
    const int tx = threadIdx.x, ty = threadIdx.y;

    if (tid < 81) w0sm[tid] = d0[tid];
    for (int i=tid;i<25*81;i+=256) w1sm[i] = d1[i];
    for (int i=tid;i<12*68;i+=256){
        int yy=i/68, xx=i-yy*68;
        int gy=y0+yy-2, gx=x0+xx-2;
        ti[yy][xx] = ((unsigned)gy<HH && (unsigned)gx<WW) ? g_inp[(size_t)n*HWSZ + (size_t)gy*WW + gx] : 0.f;
    }
    __syncthreads();

    float acc[25][2];
    #pragma unroll
    for (int t=0;t<25;t++){ acc[t][0]=0.f; acc[t][1]=0.f; }

    for (int c=0;c<9;c++){
        const int ii = c/3, jj = c%3;
        float w0[9];
        #pragma unroll
        for (int u=0;u<9;u++) w0[u] = w0sm[c*9+u];
        for (int i=tid;i<10*66;i+=256){
            int yy=i/66, xx=i-yy*66;
            int gy=y0+yy-1, gx=x0+xx-1;
            float val = 0.f;
            if ((unsigned)gy<HH && (unsigned)gx<WW){
                float ctr = ti[yy+1][xx+1];
                val = ti[yy+ii][xx+jj]*ctr;
                #pragma unroll
                for (int r=0;r<3;r++)
                #pragma unroll
                for (int s=0;s<3;s++)
                    val = fmaf(ti[yy+r][xx+s], w0[r*3+s], val);
            }
            t9[yy][xx] = val;
        }
        __syncthreads();

        #pragma unroll
        for (int r=0;r<3;r++)
        #pragma unroll
        for (int s=0;s<3;s++){
            float v0 = t9[ty + r][tx + s];
            float v1 = t9[ty + r][tx + 32 + s];
            #pragma unroll
            for (int t=0;t<25;t++){
                float wv = w1sm[t*81 + c*9 + r*3 + s];
                acc[t][0] = fmaf(wv, v0, acc[t][0]);
                acc[t][1] = fmaf(wv, v1, acc[t][1]);
            }
        }
        __syncthreads();
    }

    #pragma unroll
    for (int t=0;t<25;t++){
        const int ai = t/5, aj = t%5;
        #pragma unroll
        for (int k=0;k<2;k++){
            int lx = tx + 32*k;
            float ctr = ti[ty+2][lx+2];
            float aff = ti[ty+ai][lx+aj] * ctr;
            g_xm25[((size_t)(n*25+t))*HWSZ + (size_t)(y0+ty)*WW + x0 + lx] = aff + acc[t][k];
        }
    }
}

// ---------------- conv4d + affinity reduce + seg output ------------------------
__global__ __launch_bounds__(256) void final_k(const float* __restrict__ d4,
                                               float* __restrict__ segout)
{
    __shared__ float t25[25][10][34];
    __shared__ float ti[12][36];
    __shared__ float wsm[81];
    const int n = blockIdx.z;
    const int x0 = blockIdx.x*32, y0 = blockIdx.y*8;
    const int tid = threadIdx.y*32 + threadIdx.x;
    if (tid < 81) wsm[tid] = d4[tid];
    for (int i = tid; i < 25*340; i += 256){
        int c = i/340, rr = i - c*340, yy = rr/34, xx = rr%34;
        int gy=y0+yy-1, gx=x0+xx-1;
        t25[c][yy][xx] = ((unsigned)gy<HH && (unsigned)gx<WW) ? g_xm25[((size_t)(n*25+c))*HWSZ + gy*WW + gx] : 0.f;
    }
    for (int i=tid;i<432;i+=256){
        int yy=i/36, xx=i%36;
        int gy=y0+yy-2, gx=x0+xx-2;
        ti[yy][xx] = ((unsigned)gy<HH && (unsigned)gx<WW) ? g_inp[(size_t)n*HWSZ + gy*WW + gx] : 0.f;
    }
    __syncthreads();

    float kacc[25];
    #pragma unroll
    for (int t=0;t<25;t++) kacc[t]=0.f;

    #pragma unroll
    for (int r=0;r<3;r++)
    #pragma unroll
    for (int s=0;s<3;s++){
        float wv[9];
        #pragma unroll
        for (int p=0;p<3;p++)
        #pragma unroll
        for (int q=0;q<3;q++) wv[p*3+q] = wsm[((p*3+q)*3+r)*3 + s];
        float L[25];
        #pragma unroll
        for (int u=0;u<5;u++)
        #pragma unroll
        for (int v=0;v<5;v++) L[u*5+v] = t25[u*5+v][threadIdx.y+r][threadIdx.x+s];
        #pragma unroll
        for (int d=0;d<5;d++)
        #pragma unroll
        for (int e=0;e<5;e++)
        #pragma unroll
        for (int p=0;p<3;p++){
            int u = d-1+p; if (u < 0 || u > 4) continue;
            #pragma unroll
            for (int q=0;q<3;q++){
                int v = e-1+q; if (v < 0 || v > 4) continue;
                kacc[d*5+e] = fmaf(L[u*5+v], wv[p*3+q], kacc[d*5+e]);
            }
        }
    }
    float sum = 0.f;
    #pragma unroll
    for (int ii=0;ii<5;ii++)
    #pragma unroll
    for (int jj=0;jj<5;jj++)
        sum = fmaf(ti[threadIdx.y+ii][threadIdx.x+jj], kacc[ii*5+jj], sum);

    float o = sum / 25.0f;
    int idx = (y0+threadIdx.y)*WW + x0 + threadIdx.x;
    segout[((size_t)(n*2+0))*HWSZ + idx] = 1.0f - o;
    segout[((size_t)(n*2+1))*HWSZ + idx] = o;
}

// ---------------- top-k threshold: radix select on float keys ------------------
__device__ __forceinline__ unsigned f2key(float f){
    unsigned u = __float_as_uint(f);
    return (u & 0x80000000u) ? ~u : (u | 0x80000000u);
}
__device__ __forceinline__ float key2f(unsigned k){
    unsigned u = (k & 0x80000000u) ? (k & 0x7fffffffu) : ~k;
    return __uint_as_float(u);
}

__global__ __launch_bounds__(256) void hist_k(const float* __restrict__ seg, int shift)
{
    __shared__ unsigned hh[256];
    const int j = blockIdx.y;
    hh[threadIdx.x]=0u;
    __syncthreads();
    const bool first = (shift == 24);
    unsigned pfx = first ? 0u : g_prefix[j];
    unsigned mask = first ? 0u : (0xFFFFFFFFu << (shift+8));
    const float4* p = (const float4*)(seg + (size_t)j*HWSZ);
    for (int i = blockIdx.x*256 + threadIdx.x; i < HWSZ/4; i += 64*256){
        float4 v = p[i];
        unsigned k0 = f2key(v.x), k1 = f2key(v.y), k2 = f2key(v.z), k3 = f2key(v.w);
        if (first || (k0 & mask) == pfx) atomicAdd(&hh[(k0>>shift)&255u], 1u);
        if (first || (k1 & mask) == pfx) atomicAdd(&hh[(k1>>shift)&255u], 1u);
        if (first || (k2 & mask) == pfx) atomicAdd(&hh[(k2>>shift)&255u], 1u);
        if (first || (k3 & mask) == pfx) atomicAdd(&hh[(k3>>shift)&255u], 1u);
    }
    __syncthreads();
    if (hh[threadIdx.x]) atomicAdd(&g_hist[j][threadIdx.x], hh[threadIdx.x]);
}

__global__ void select_k(const float* __restrict__ ratio, int shift,
                         int first, int last)
{
    int j = threadIdx.x;
    if (j >= 4) return;
    int rem; unsigned pfx;
    if (first){
        int n = j >> 1;
        float fp = floorf(ratio[n]*(float)HWSZ);
        int k = (int)floorf(fp*0.1f);
        rem = k-1; if (rem < 0) rem = 0;
        pfx = 0u;
    } else {
        rem = g_remain[j]; pfx = g_prefix[j];
    }
    int done = 0;
    for (int b=255;b>=0;b--){
        unsigned c = g_hist[j][b];
        if (!done){
            if ((int)c > rem){ pfx |= ((unsigned)b)<<shift; done=1; }
            else rem -= (int)c;
        }
        g_hist[j][b]=0u;
    }
    g_prefix[j]=pfx; g_remain[j]=rem;
    if (last) g_thr[j] = key2f(pfx);
}

// ---------------- host orchestration -------------------------------------------
struct Ptrs { float *feat, *aux, *auxb1; };

template<bool ERASE>
static void run_pipeline(const float* img, const float* seg, float* seg_out,
                         const float* w1, const float* wa, const float* wout,
                         const float* b1w, const float* b1g, const float* b1b,
                         const float* b2w, const float* b2g, const float* b2b,
                         const float* d0w, const float* d1w, const float* d4w,
                         const Ptrs& P)
{
    dim3 blk(32,8);
    dualconv3_k<ERASE><<<dim3(16,16,NB*4), blk>>>(img, seg, w1, wa, P.feat, P.aux);
    conv32_k<<<dim3(16,16,NB*2), blk>>>(P.aux, b1w, P.auxb1);
    stats2_k<<<32,256>>>(b1g, b1b);
    b2_k<<<NHW/1024, 256>>>(b2w);
    wout_inp_k<<<dim3(8,32,NB), blk>>>(P.feat, wout, b2g, b2b);
    xm25f_k<<<dim3(8,64,NB), blk>>>(d0w, d1w);
    final_k<<<dim3(16,64,NB), blk>>>(d4w, seg_out);
}

extern "C" void kernel_launch(void* const* d_in, const int* in_sizes, int n_in,
                              void* d_out, int out_size)
{
    const float* x     = (const float*)d_in[0];
    const float* ratio = (const float*)d_in[1];
    const float* w1    = (const float*)d_in[2];
    const float* wa    = (const float*)d_in[3];
    const float* wout  = (const float*)d_in[4];
    const float* b1w   = (const float*)d_in[5];
    const float* b1g   = (const float*)d_in[6];
    const float* b1b   = (const float*)d_in[7];
    const float* b2w   = (const float*)d_in[8];
    const float* b2g   = (const float*)d_in[9];
    const float* b2b   = (const float*)d_in[10];
    const float* d0w   = (const float*)d_in[11];
    const float* d1w   = (const float*)d_in[12];
    const float* d4w   = (const float*)d_in[13];
    float* out = (float*)d_out;

    Ptrs P;
    void* p;
    cudaGetSymbolAddress(&p, g_feat);   P.feat   = (float*)p;
    cudaGetSymbolAddress(&p, g_aux);    P.aux    = (float*)p;
    cudaGetSymbolAddress(&p, g_auxb1);  P.auxb1  = (float*)p;

    // pipeline 1 -> x1 (first half of output)
    run_pipeline<false>(x, nullptr, out, w1, wa, wout, b1w, b1g, b1b,
                        b2w, b2g, b2b, d0w, d1w, d4w, P);

    // erasing threshold: per-(n,c) radix select
    for (int pass=0; pass<4; ++pass){
        int shift = 24 - 8*pass;
        hist_k<<<dim3(64,4), 256>>>(out, shift);
        select_k<<<1,4>>>(ratio, shift, pass==0 ? 1 : 0, pass==3 ? 1 : 0);
    }

    // pipeline 2 (erase fused into its dual conv3) -> x2 (second half)
    run_pipeline<true>(x, out, out + (size_t)NB*2*HWSZ, w1, wa, wout,
                       b1w, b1g, b1b, b2w, b2g, b2b, d0w, d1w, d4w, P);
}

// round 15
// speedup vs baseline: 1.9086x; 1.0006x over previous
#include <cuda_runtime.h>
#include <math.h>

#define HH 512
#define WW 512
#define NB 2
#define HWSZ (HH*WW)          // 262144
#define NHW (NB*HWSZ)         // 524288

// ---------------- scratch (device globals; no allocation allowed) -------------
__device__ float g_feat [NB*32*HWSZ];
__device__ float g_aux  [NB*32*HWSZ];
__device__ float g_auxb1[NB*32*HWSZ];
__device__ float g_z    [NHW];
__device__ float g_inp  [NHW];
__device__ float g_xm25 [NB*25*HWSZ];
__device__ float g_part [32*512*2];
__device__ float g_scale1[32], g_shift1[32];
__device__ unsigned g_hist[4][256];
__device__ unsigned g_prefix[4];
__device__ int      g_remain[4];
__device__ float    g_thr[4];

// ---------------- fused dual 3x3 conv (3->32 twice): 16 oc x 4 rows/thread ----
template<bool ERASE>
__global__ __launch_bounds__(256) void dualconv3_k(
    const float* __restrict__ img, const float* __restrict__ seg,
    const float* __restrict__ w1, const float* __restrict__ wa,
    float* __restrict__ feat, float* __restrict__ aux)
{
    __shared__ float tile[2][34][34];
    __shared__ float wsm[16*27];
    const int tid = threadIdx.y*32 + threadIdx.x;
    const int tx = threadIdx.x, ty = threadIdx.y;
    const int grp = blockIdx.z & 3;
    const int n   = blockIdx.z >> 2;
    const int oc0 = grp*8;
    const int x0 = blockIdx.x*32, y0 = blockIdx.y*32;
    const int TSZ = 34*34;
    const int NLD = 5;

    for (int i = tid; i < 16*27; i += 256){
        int o = i/27, rr = i - o*27;
        wsm[i] = (o < 8) ? w1[(oc0+o)*27 + rr] : wa[(oc0+o-8)*27 + rr];
    }

    int off[NLD]; unsigned vmask = 0u, emask = 0u;
    #pragma unroll
    for (int j=0;j<NLD;j++){
        int i = tid + j*256;
        int yy = i/34, xx = i - yy*34;
        int gy = y0+yy-1, gx = x0+xx-1;
        bool v = (i < TSZ) && ((unsigned)gy < HH) && ((unsigned)gx < WW);
        off[j] = v ? (gy*WW + gx) : 0;
        if (v) vmask |= (1u<<j);
    }
    if (ERASE){
        float t0 = g_thr[n*2+0], t1 = g_thr[n*2+1];
        #pragma unroll
        for (int j=0;j<NLD;j++){
            if ((vmask>>j)&1u){
                float s0 = seg[((size_t)(n*2+0))*HWSZ + off[j]];
                float s1 = seg[((size_t)(n*2+1))*HWSZ + off[j]];
                if (s0 > t0 || s1 > t1) emask |= (1u<<j);
            }
        }
    }

    {
        const float* src = img + (size_t)(n*3)*HWSZ;
        float rld[NLD];
        #pragma unroll
        for (int j=0;j<NLD;j++)
            rld[j] = (((vmask>>j)&1u) && !((emask>>j)&1u)) ? src[off[j]] : 0.f;
        float* tb = &tile[0][0][0];
        #pragma unroll
        for (int j=0;j<NLD;j++){ int i = tid + j*256; if (i < TSZ) tb[i] = rld[j]; }
    }
    __syncthreads();

    float acc[16][4];
    #pragma unroll
    for (int o=0;o<16;o++)
        #pragma unroll
        for (int k=0;k<4;k++) acc[o][k]=0.f;

    for (int c = 0; c < 3; c++){
        const int cur = c & 1;
        float rld[NLD];
        if (c+1 < 3){
            const float* src = img + (size_t)(n*3 + c+1)*HWSZ;
            #pragma unroll
            for (int j=0;j<NLD;j++)
                rld[j] = (((vmask>>j)&1u) && !((emask>>j)&1u)) ? src[off[j]] : 0.f;
        }
        #pragma unroll
        for (int r=0;r<3;r++)
        #pragma unroll
        for (int s=0;s<3;s++){
            float wv[16];
            #pragma unroll
            for (int o=0;o<16;o++) wv[o] = wsm[o*27 + c*9 + r*3 + s];
            #pragma unroll
            for (int k=0;k<4;k++){
                float v = tile[cur][ty + 8*k + r][tx + s];
                #pragma unroll
                for (int o=0;o<16;o++) acc[o][k] = fmaf(wv[o], v, acc[o][k]);
            }
        }
        if (c+1 < 3){
            float* tb = &tile[cur^1][0][0];
            #pragma unroll
            for (int j=0;j<NLD;j++){ int i = tid + j*256; if (i < TSZ) tb[i] = rld[j]; }
        }
        __syncthreads();
    }

    #pragma unroll
    for (int o=0;o<16;o++)
    #pragma unroll
    for (int k=0;k<4;k++){
        float v = fmaxf(acc[o][k], 0.f);
        size_t idx = (size_t)(y0+ty+8*k)*WW + x0 + tx;
        if (o < 8) feat[((size_t)(n*32 + oc0 + o  ))*HWSZ + idx] = v;
        else       aux [((size_t)(n*32 + oc0 + o-8))*HWSZ + idx] = v;
    }
}

// ---------------- 32->32 3x3 conv: 16 oc x 4 rows/thread, fused BN partials ----
// tile 32x32; 2 oc-groups; 4-buffer rotation: 2 channels per __syncthreads.
__global__ __launch_bounds__(256,2) void conv32_k(
    const float* __restrict__ in, const float* __restrict__ wt,
    float* __restrict__ out)
{
    __shared__ float tile[4][34][34];
    __shared__ float wsm[16*32*9];
    const int tid = threadIdx.y*32 + threadIdx.x;
    const int tx = threadIdx.x, ty = threadIdx.y;
    const int grp = blockIdx.z & 1;
    const int n   = blockIdx.z >> 1;
    const int oc0 = grp*16;
    const int x0 = blockIdx.x*32, y0 = blockIdx.y*32;
    const int TSZ = 34*34;
    const int NLD = 5;

    for (int i = tid; i < 16*32*9; i += 256) wsm[i] = wt[oc0*32*9 + i];

    int off[NLD]; unsigned vmask = 0u;
    #pragma unroll
    for (int j=0;j<NLD;j++){
        int i = tid + j*256;
        int yy = i/34, xx = i - yy*34;
        int gy = y0+yy-1, gx = x0+xx-1;
        bool v = (i < TSZ) && ((unsigned)gy < HH) && ((unsigned)gx < WW);
        off[j] = v ? (gy*WW + gx) : 0;
        if (v) vmask |= (1u<<j);
    }

    // load channels 0 and 1 into buffers 0 and 1
    {
        const float* s0 = in + (size_t)(n*32 + 0)*HWSZ;
        const float* s1 = in + (size_t)(n*32 + 1)*HWSZ;
        float rA[NLD], rB[NLD];
        #pragma unroll
        for (int j=0;j<NLD;j++){
            rA[j] = ((vmask>>j)&1u) ? s0[off[j]] : 0.f;
            rB[j] = ((vmask>>j)&1u) ? s1[off[j]] : 0.f;
        }
        float* tA = &tile[0][0][0];
        float* tB = &tile[1][0][0];
        #pragma unroll
        for (int j=0;j<NLD;j++){
            int i = tid + j*256;
            if (i < TSZ){ tA[i] = rA[j]; tB[i] = rB[j]; }
        }
    }
    __syncthreads();

    float acc[16][4];
    #pragma unroll
    for (int o=0;o<16;o++)
        #pragma unroll
        for (int k=0;k<4;k++) acc[o][k]=0.f;

    for (int c = 0; c < 32; c += 2){
        float rA[NLD], rB[NLD];
        if (c+2 < 32){
            const float* sA = in + (size_t)(n*32 + c+2)*HWSZ;
            const float* sB = in + (size_t)(n*32 + c+3)*HWSZ;
            #pragma unroll
            for (int j=0;j<NLD;j++){
                rA[j] = ((vmask>>j)&1u) ? sA[off[j]] : 0.f;
                rB[j] = ((vmask>>j)&1u) ? sB[off[j]] : 0.f;
            }
        }
        // FMA channel c (buffer c&3) then c+1 (buffer (c+1)&3)
        #pragma unroll
        for (int cc=0;cc<2;cc++){
            const int ch  = c + cc;
            const int buf = ch & 3;
            #pragma unroll
            for (int r=0;r<3;r++)
            #pragma unroll
            for (int s=0;s<3;s++){
                float wv[16];
                #pragma unroll
                for (int o=0;o<16;o++) wv[o] = wsm[(o*32+ch)*9 + r*3 + s];
                #pragma unroll
                for (int k=0;k<4;k++){
                    float v = tile[buf][ty + 8*k + r][tx + s];
                    #pragma unroll
                    for (int o=0;o<16;o++) acc[o][k] = fmaf(wv[o], v, acc[o][k]);
                }
            }
        }
        if (c+2 < 32){
            float* tA = &tile[(c+2)&3][0][0];
            float* tB = &tile[(c+3)&3][0][0];
            #pragma unroll
            for (int j=0;j<NLD;j++){
                int i = tid + j*256;
                if (i < TSZ){ tA[i] = rA[j]; tB[i] = rB[j]; }
            }
        }
        __syncthreads();
    }

    #pragma unroll
    for (int o=0;o<16;o++)
    #pragma unroll
    for (int k=0;k<4;k++)
        out[((size_t)(n*32 + oc0 + o))*HWSZ + (size_t)(y0+ty+8*k)*WW + x0 + tx] = acc[o][k];

    // deterministic per-block BN partials (one oc at a time: no reg blowup)
    float* red = &tile[0][0][0];
    #pragma unroll
    for (int o=0;o<16;o++){
        float sv=0.f, qv=0.f;
        #pragma unroll
        for (int k=0;k<4;k++){ float v=acc[o][k]; sv+=v; qv=fmaf(v,v,qv); }
        #pragma unroll
        for (int d=16; d>0; d>>=1){
            sv += __shfl_down_sync(0xffffffffu, sv, d);
            qv += __shfl_down_sync(0xffffffffu, qv, d);
        }
        if (tx == 0){ red[o*8+ty]=sv; red[128+o*8+ty]=qv; }
    }
    __syncthreads();
    if (tid < 16){
        float S=0.f, Q=0.f;
        #pragma unroll
        for (int w=0;w<8;w++){ S+=red[tid*8+w]; Q+=red[128+tid*8+w]; }
        int p = n*256 + blockIdx.y*gridDim.x + blockIdx.x;  // < 512
        g_part[((oc0+tid)*512+p)*2+0] = S;
        g_part[((oc0+tid)*512+p)*2+1] = Q;
    }
}

// ---------------- reduce conv32 partials (512/channel) -> scale1/shift1 --------
__global__ __launch_bounds__(256) void stats2_k(const float* __restrict__ g,
                                                const float* __restrict__ b)
{
    const int c = blockIdx.x;
    __shared__ float ss[256], qq[256];
    ss[threadIdx.x] = g_part[(c*512+threadIdx.x)*2+0] + g_part[(c*512+threadIdx.x+256)*2+0];
    qq[threadIdx.x] = g_part[(c*512+threadIdx.x)*2+1] + g_part[(c*512+threadIdx.x+256)*2+1];
    __syncthreads();
    for (int o=128;o>0;o>>=1){
        if (threadIdx.x < o){ ss[threadIdx.x]+=ss[threadIdx.x+o]; qq[threadIdx.x]+=qq[threadIdx.x+o]; }
        __syncthreads();
    }
    if (threadIdx.x==0){
        float mean = ss[0]/(float)NHW;
        float var  = qq[0]/(float)NHW - mean*mean;
        float sc = g[c]*rsqrtf(var + 1e-5f);
        g_scale1[c]=sc; g_shift1[c]=b[c]-mean*sc;
    }
}

// ---------------- z = sum_c relu(bn(auxb1_c)) * b2w_c, float4 (4 px/thread) ----
__global__ __launch_bounds__(256) void b2_k(const float* __restrict__ w2)
{
    __shared__ float s[32], h[32], ww[32];
    if (threadIdx.x < 32){ s[threadIdx.x]=g_scale1[threadIdx.x];
                           h[threadIdx.x]=g_shift1[threadIdx.x];
                           ww[threadIdx.x]=w2[threadIdx.x]; }
    __syncthreads();
    int base = (blockIdx.x*256 + threadIdx.x)*4;
    int n = base / HWSZ, r = base - n*HWSZ;
    float4 acc = make_float4(0.f,0.f,0.f,0.f);
    #pragma unroll
    for (int c=0;c<32;c++){
        float4 v = *(const float4*)&g_auxb1[((size_t)(n*32+c))*HWSZ + r];
        float sc = s[c], hc = h[c], wc = ww[c];
        acc.x = fmaf(fmaxf(fmaf(v.x,sc,hc),0.f), wc, acc.x);
        acc.y = fmaf(fmaxf(fmaf(v.y,sc,hc),0.f), wc, acc.y);
        acc.z = fmaf(fmaxf(fmaf(v.z,sc,hc),0.f), wc, acc.z);
        acc.w = fmaf(fmaxf(fmaf(v.w,sc,hc),0.f), wc, acc.w);
    }
    *(float4*)&g_z[base] = acc;
    float sv = acc.x + acc.y + acc.z + acc.w;
    float qv = fmaf(acc.x,acc.x, fmaf(acc.y,acc.y, fmaf(acc.z,acc.z, acc.w*acc.w)));
    __shared__ float ss[256], qq[256];
    ss[threadIdx.x]=sv; qq[threadIdx.x]=qv;
    __syncthreads();
    for (int o=128;o>0;o>>=1){
        if (threadIdx.x < o){ ss[threadIdx.x]+=ss[threadIdx.x+o]; qq[threadIdx.x]+=qq[threadIdx.x+o]; }
        __syncthreads();
    }
    if (threadIdx.x==0){
        g_part[blockIdx.x*2+0]=ss[0];
        g_part[blockIdx.x*2+1]=qq[0];
    }
}

// ---------------- x1 = conv(feat, w_out) ; inp = x1 + relu(bn(z)) --------------
// folded z-BN stats; 2px x 2rows per thread, float2 smem reads; tile 64x16
__global__ __launch_bounds__(256) void wout_inp_k(
    const float* __restrict__ feat, const float* __restrict__ wt,
    const float* __restrict__ b2g, const float* __restrict__ b2b)
{
    __shared__ float tile[2][18][68];
    __shared__ float wsm[32*9];
    __shared__ float rs[256], rq[256];
    const int tid = threadIdx.y*32 + threadIdx.x;
    const int tx = threadIdx.x, ty = threadIdx.y;
    const int n = blockIdx.z;
    const int x0 = blockIdx.x*64, y0 = blockIdx.y*16;
    const int TSZ = 18*66;
    const int NLD = 5;

    {
        float s = g_part[tid*2+0] + g_part[(tid+256)*2+0];
        float q = g_part[tid*2+1] + g_part[(tid+256)*2+1];
        rs[tid]=s; rq[tid]=q;
        __syncthreads();
        for (int o=128;o>0;o>>=1){
            if (tid < o){ rs[tid]+=rs[tid+o]; rq[tid]+=rq[tid+o]; }
            __syncthreads();
        }
        if (tid==0){
            float mean = rs[0]/(float)NHW;
            float var  = rq[0]/(float)NHW - mean*mean;
            float sc = b2g[0]*rsqrtf(var + 1e-5f);
            rs[0]=sc; rq[0]=b2b[0]-mean*sc;
        }
        __syncthreads();
    }
    const float s2 = rs[0], h2 = rq[0];

    for (int i = tid; i < 288; i += 256) wsm[i] = wt[i];

    int off[NLD]; unsigned vmask = 0u;
    #pragma unroll
    for (int j=0;j<NLD;j++){
        int i = tid + j*256;
        int yy = i/66, xx = i - yy*66;
        int gy = y0+yy-1, gx = x0+xx-1;
        bool v = (i < TSZ) && ((unsigned)gy < HH) && ((unsigned)gx < WW);
        off[j] = v ? (gy*WW + gx) : 0;
        if (v) vmask |= (1u<<j);
    }
    {
        const float* src = feat + (size_t)(n*32)*HWSZ;
        float rld[NLD];
        #pragma unroll
        for (int j=0;j<NLD;j++) rld[j] = ((vmask>>j)&1u) ? src[off[j]] : 0.f;
        float* tb = &tile[0][0][0];
        #pragma unroll
        for (int j=0;j<NLD;j++){
            int i = tid + j*256;
            if (i < TSZ){ int yy=i/66, xx=i-yy*66; tb[yy*68+xx] = rld[j]; }
        }
    }
    __syncthreads();

    float acc[2][2];
    acc[0][0]=acc[0][1]=acc[1][0]=acc[1][1]=0.f;

    for (int c = 0; c < 32; c++){
        const int cur = c & 1;
        float rld[NLD];
        if (c+1 < 32){
            const float* src = feat + (size_t)(n*32 + c+1)*HWSZ;
            #pragma unroll
            for (int j=0;j<NLD;j++) rld[j] = ((vmask>>j)&1u) ? src[off[j]] : 0.f;
        }
        #pragma unroll
        for (int r=0;r<3;r++){
            float w0 = wsm[c*9 + r*3 + 0];
            float w1 = wsm[c*9 + r*3 + 1];
            float w2 = wsm[c*9 + r*3 + 2];
            #pragma unroll
            for (int k=0;k<2;k++){
                const int row = ty + 8*k + r;
                float2 A = *(const float2*)&tile[cur][row][2*tx];
                float2 B = *(const float2*)&tile[cur][row][2*tx+2];
                acc[k][0] = fmaf(w0, A.x, acc[k][0]);
                acc[k][0] = fmaf(w1, A.y, acc[k][0]);
                acc[k][0] = fmaf(w2, B.x, acc[k][0]);
                acc[k][1] = fmaf(w0, A.y, acc[k][1]);
                acc[k][1] = fmaf(w1, B.x, acc[k][1]);
                acc[k][1] = fmaf(w2, B.y, acc[k][1]);
            }
        }
        if (c+1 < 32){
            float* tb = &tile[cur^1][0][0];
            #pragma unroll
            for (int j=0;j<NLD;j++){
                int i = tid + j*256;
                if (i < TSZ){ int yy=i/66, xx=i-yy*66; tb[yy*68+xx] = rld[j]; }
            }
        }
        __syncthreads();
    }

    #pragma unroll
    for (int k=0;k<2;k++){
        int idx = (y0+ty+8*k)*WW + x0 + 2*tx;
        float2 zz = *(const float2*)&g_z[(size_t)n*HWSZ + idx];
        float2 o;
        o.x = acc[k][0] + fmaxf(zz.x*s2 + h2, 0.f);
        o.y = acc[k][1] + fmaxf(zz.y*s2 + h2, 0.f);
        *(float2*)&g_inp[(size_t)n*HWSZ + idx] = o;
    }
}

// ---------------- xm25 = aff5(inp) + conv(xm9(inp), d1), xm9 fused -------------
__global__ __launch_bounds__(256) void xm25f_k(const float* __restrict__ d0,
                                               const float* __restrict__ d1)
{
    __shared__ float ti[12][68];
    __shared__ float t9[10][68];
    __shared__ float w0sm[81];
    __shared__ float w1sm[25*81];
    const int n = blockIdx.z;
    const int x0 = blockIdx.x*64, y0 = blockIdx.y*8;
    const int tid = threadIdx.y*32 + threadIdx.x;
    const int tx = threadIdx.x, ty = threadIdx.y;

    if (tid < 81) w0sm[tid] = d0[tid];
    for (int i=tid;i<25*81;i+=256) w1sm[i] = d1[i];
    for (int i=tid;i<12*68;i+=256){
        int yy=i/68, xx=i-yy*68;
        int gy=y0+yy-2, gx=x0+xx-2;
        ti[yy][xx] = ((unsigned)gy<HH && (unsigned)gx<WW) ? g_inp[(size_t)n*HWSZ + (size_t)gy*WW + gx] : 0.f;
    }
    __syncthreads();

    float acc[25][2];
    #pragma unroll
    for (int t=0;t<25;t++){ acc[t][0]=0.f; acc[t][1]=0.f; }

    for (int c=0;c<9;c++){
        const int ii = c/3, jj = c%3;
        float w0[9];
        #pragma unroll
        for (int u=0;u<9;u++) w0[u] = w0sm[c*9+u];
        for (int i=tid;i<10*66;i+=256){
            int yy=i/66, xx=i-yy*66;
            int gy=y0+yy-1, gx=x0+xx-1;
            float val = 0.f;
            if ((unsigned)gy<HH && (unsigned)gx<WW){
                float ctr = ti[yy+1][xx+1];
                val = ti[yy+ii][xx+jj]*ctr;
                #pragma unroll
                for (int r=0;r<3;r++)
                #pragma unroll
                for (int s=0;s<3;s++)
                    val = fmaf(ti[yy+r][xx+s], w0[r*3+s], val);
            }
            t9[yy][xx] = val;
        }
        __syncthreads();

        #pragma unroll
        for (int r=0;r<3;r++)
        #pragma unroll
        for (int s=0;s<3;s++){
            float v0 = t9[ty + r][tx + s];
            float v1 = t9[ty + r][tx + 32 + s];
            #pragma unroll
            for (int t=0;t<25;t++){
                float wv = w1sm[t*81 + c*9 + r*3 + s];
                acc[t][0] = fmaf(wv, v0, acc[t][0]);
                acc[t][1] = fmaf(wv, v1, acc[t][1]);
            }
        }
        __syncthreads();
    }

    #pragma unroll
    for (int t=0;t<25;t++){
        const int ai = t/5, aj = t%5;
        #pragma unroll
        for (int k=0;k<2;k++){
            int lx = tx + 32*k;
            float ctr = ti[ty+2][lx+2];
            float aff = ti[ty+ai][lx+aj] * ctr;
            g_xm25[((size_t)(n*25+t))*HWSZ + (size_t)(y0+ty)*WW + x0 + lx] = aff + acc[t][k];
        }
    }
}

// ---------------- conv4d + affinity reduce + seg output ------------------------
__global__ __launch_bounds__(256) void final_k(const float* __restrict__ d4,
                                               float* __restrict__ segout)
{
    __shared__ float t25[25][10][34];
    __shared__ float ti[12][36];
    __shared__ float wsm[81];
    const int n = blockIdx.z;
    const int x0 = blockIdx.x*32, y0 = blockIdx.y*8;
    const int tid = threadIdx.y*32 + threadIdx.x;
    if (tid < 81) wsm[tid] = d4[tid];
    for (int i = tid; i < 25*340; i += 256){
        int c = i/340, rr = i - c*340, yy = rr/34, xx = rr%34;
        int gy=y0+yy-1, gx=x0+xx-1;
        t25[c][yy][xx] = ((unsigned)gy<HH && (unsigned)gx<WW) ? g_xm25[((size_t)(n*25+c))*HWSZ + gy*WW + gx] : 0.f;
    }
    for (int i=tid;i<432;i+=256){
        int yy=i/36, xx=i%36;
        int gy=y0+yy-2, gx=x0+xx-2;
        ti[yy][xx] = ((unsigned)gy<HH && (unsigned)gx<WW) ? g_inp[(size_t)n*HWSZ + gy*WW + gx] : 0.f;
    }
    __syncthreads();

    float kacc[25];
    #pragma unroll
    for (int t=0;t<25;t++) kacc[t]=0.f;

    #pragma unroll
    for (int r=0;r<3;r++)
    #pragma unroll
    for (int s=0;s<3;s++){
        float wv[9];
        #pragma unroll
        for (int p=0;p<3;p++)
        #pragma unroll
        for (int q=0;q<3;q++) wv[p*3+q] = wsm[((p*3+q)*3+r)*3 + s];
        float L[25];
        #pragma unroll
        for (int u=0;u<5;u++)
        #pragma unroll
        for (int v=0;v<5;v++) L[u*5+v] = t25[u*5+v][threadIdx.y+r][threadIdx.x+s];
        #pragma unroll
        for (int d=0;d<5;d++)
        #pragma unroll
        for (int e=0;e<5;e++)
        #pragma unroll
        for (int p=0;p<3;p++){
            int u = d-1+p; if (u < 0 || u > 4) continue;
            #pragma unroll
            for (int q=0;q<3;q++){
                int v = e-1+q; if (v < 0 || v > 4) continue;
                kacc[d*5+e] = fmaf(L[u*5+v], wv[p*3+q], kacc[d*5+e]);
            }
        }
    }
    float sum = 0.f;
    #pragma unroll
    for (int ii=0;ii<5;ii++)
    #pragma unroll
    for (int jj=0;jj<5;jj++)
        sum = fmaf(ti[threadIdx.y+ii][threadIdx.x+jj], kacc[ii*5+jj], sum);

    float o = sum / 25.0f;
    int idx = (y0+threadIdx.y)*WW + x0 + threadIdx.x;
    segout[((size_t)(n*2+0))*HWSZ + idx] = 1.0f - o;
    segout[((size_t)(n*2+1))*HWSZ + idx] = o;
}

// ---------------- top-k threshold: radix select on float keys ------------------
__device__ __forceinline__ unsigned f2key(float f){
    unsigned u = __float_as_uint(f);
    return (u & 0x80000000u) ? ~u : (u | 0x80000000u);
}
__device__ __forceinline__ float key2f(unsigned k){
    unsigned u = (k & 0x80000000u) ? (k & 0x7fffffffu) : ~k;
    return __uint_as_float(u);
}

__global__ __launch_bounds__(256) void hist_k(const float* __restrict__ seg, int shift)
{
    __shared__ unsigned hh[256];
    const int j = blockIdx.y;
    hh[threadIdx.x]=0u;
    __syncthreads();
    const bool first = (shift == 24);
    unsigned pfx = first ? 0u : g_prefix[j];
    unsigned mask = first ? 0u : (0xFFFFFFFFu << (shift+8));
    const float4* p = (const float4*)(seg + (size_t)j*HWSZ);
    for (int i = blockIdx.x*256 + threadIdx.x; i < HWSZ/4; i += 64*256){
        float4 v = p[i];
        unsigned k0 = f2key(v.x), k1 = f2key(v.y), k2 = f2key(v.z), k3 = f2key(v.w);
        if (first || (k0 & mask) == pfx) atomicAdd(&hh[(k0>>shift)&255u], 1u);
        if (first || (k1 & mask) == pfx) atomicAdd(&hh[(k1>>shift)&255u], 1u);
        if (first || (k2 & mask) == pfx) atomicAdd(&hh[(k2>>shift)&255u], 1u);
        if (first || (k3 & mask) == pfx) atomicAdd(&hh[(k3>>shift)&255u], 1u);
    }
    __syncthreads();
    if (hh[threadIdx.x]) atomicAdd(&g_hist[j][threadIdx.x], hh[threadIdx.x]);
}

__global__ void select_k(const float* __restrict__ ratio, int shift,
                         int first, int last)
{
    int j = threadIdx.x;
    if (j >= 4) return;
    int rem; unsigned pfx;
    if (first){
        int n = j >> 1;
        float fp = floorf(ratio[n]*(float)HWSZ);
        int k = (int)floorf(fp*0.1f);
        rem = k-1; if (rem < 0) rem = 0;
        pfx = 0u;
    } else {
        rem = g_remain[j]; pfx = g_prefix[j];
    }
    int done = 0;
    for (int b=255;b>=0;b--){
        unsigned c = g_hist[j][b];
        if (!done){
            if ((int)c > rem){ pfx |= ((unsigned)b)<<shift; done=1; }
            else rem -= (int)c;
        }
        g_hist[j][b]=0u;
    }
    g_prefix[j]=pfx; g_remain[j]=rem;
    if (last) g_thr[j] = key2f(pfx);
}

// ---------------- host orchestration -------------------------------------------
struct Ptrs { float *feat, *aux, *auxb1; };

template<bool ERASE>
static void run_pipeline(const float* img, const float* seg, float* seg_out,
                         const float* w1, const float* wa, const float* wout,
                         const float* b1w, const float* b1g, const float* b1b,
                         const float* b2w, const float* b2g, const float* b2b,
                         const float* d0w, const float* d1w, const float* d4w,
                         const Ptrs& P)
{
    dim3 blk(32,8);
    dualconv3_k<ERASE><<<dim3(16,16,NB*4), blk>>>(img, seg, w1, wa, P.feat, P.aux);
    conv32_k<<<dim3(16,16,NB*2), blk>>>(P.aux, b1w, P.auxb1);
    stats2_k<<<32,256>>>(b1g, b1b);
    b2_k<<<NHW/1024, 256>>>(b2w);
    wout_inp_k<<<dim3(8,32,NB), blk>>>(P.feat, wout, b2g, b2b);
    xm25f_k<<<dim3(8,64,NB), blk>>>(d0w, d1w);
    final_k<<<dim3(16,64,NB), blk>>>(d4w, seg_out);
}

extern "C" void kernel_launch(void* const* d_in, const int* in_sizes, int n_in,
                              void* d_out, int out_size)
{
    const float* x     = (const float*)d_in[0];
    const float* ratio = (const float*)d_in[1];
    const float* w1    = (const float*)d_in[2];
    const float* wa    = (const float*)d_in[3];
    const float* wout  = (const float*)d_in[4];
    const float* b1w   = (const float*)d_in[5];
    const float* b1g   = (const float*)d_in[6];
    const float* b1b   = (const float*)d_in[7];
    const float* b2w   = (const float*)d_in[8];
    const float* b2g   = (const float*)d_in[9];
    const float* b2b   = (const float*)d_in[10];
    const float* d0w   = (const float*)d_in[11];
    const float* d1w   = (const float*)d_in[12];
    const float* d4w   = (const float*)d_in[13];
    float* out = (float*)d_out;

    Ptrs P;
    void* p;
    cudaGetSymbolAddress(&p, g_feat);   P.feat   = (float*)p;
    cudaGetSymbolAddress(&p, g_aux);    P.aux    = (float*)p;
    cudaGetSymbolAddress(&p, g_auxb1);  P.auxb1  = (float*)p;

    // pipeline 1 -> x1 (first half of output)
    run_pipeline<false>(x, nullptr, out, w1, wa, wout, b1w, b1g, b1b,
                        b2w, b2g, b2b, d0w, d1w, d4w, P);

    // erasing threshold: per-(n,c) radix select
    for (int pass=0; pass<4; ++pass){
        int shift = 24 - 8*pass;
        hist_k<<<dim3(64,4), 256>>>(out, shift);
        select_k<<<1,4>>>(ratio, shift, pass==0 ? 1 : 0, pass==3 ? 1 : 0);
    }

    // pipeline 2 (erase fused into its dual conv3) -> x2 (second half)
    run_pipeline<true>(x, out, out + (size_t)NB*2*HWSZ, w1, wa, wout,
                       b1w, b1g, b1b, b2w, b2g, b2b, d0w, d1w, d4w, P);
}

// round 16
// speedup vs baseline: 1.9479x; 1.0206x over previous
#include <cuda_runtime.h>
#include <math.h>

#define HH 512
#define WW 512
#define NB 2
#define HWSZ (HH*WW)          // 262144
#define NHW (NB*HWSZ)         // 524288

// ---------------- scratch (device globals; no allocation allowed) -------------
__device__ float g_feat [NB*32*HWSZ];
__device__ float g_aux  [NB*32*HWSZ];
__device__ float g_auxb1[NB*32*HWSZ];
__device__ float g_z    [NHW];
__device__ float g_inp  [NHW];
__device__ float g_xm25 [NB*25*HWSZ];
__device__ float g_part [32*512*2];
__device__ float g_scale1[32], g_shift1[32];
__device__ unsigned g_hist[4][2048];
__device__ unsigned g_prefix[4];
__device__ int      g_remain[4];
__device__ float    g_thr[4];

// ---------------- fused dual 3x3 conv (3->32 twice): 16 oc x 4 rows/thread ----
template<bool ERASE>
__global__ __launch_bounds__(256) void dualconv3_k(
    const float* __restrict__ img, const float* __restrict__ seg,
    const float* __restrict__ w1, const float* __restrict__ wa,
    float* __restrict__ feat, float* __restrict__ aux)
{
    __shared__ float tile[2][34][34];
    __shared__ float wsm[16*27];
    const int tid = threadIdx.y*32 + threadIdx.x;
    const int tx = threadIdx.x, ty = threadIdx.y;
    const int grp = blockIdx.z & 3;
    const int n   = blockIdx.z >> 2;
    const int oc0 = grp*8;
    const int x0 = blockIdx.x*32, y0 = blockIdx.y*32;
    const int TSZ = 34*34;
    const int NLD = 5;

    for (int i = tid; i < 16*27; i += 256){
        int o = i/27, rr = i - o*27;
        wsm[i] = (o < 8) ? w1[(oc0+o)*27 + rr] : wa[(oc0+o-8)*27 + rr];
    }

    int off[NLD]; unsigned vmask = 0u, emask = 0u;
    #pragma unroll
    for (int j=0;j<NLD;j++){
        int i = tid + j*256;
        int yy = i/34, xx = i - yy*34;
        int gy = y0+yy-1, gx = x0+xx-1;
        bool v = (i < TSZ) && ((unsigned)gy < HH) && ((unsigned)gx < WW);
        off[j] = v ? (gy*WW + gx) : 0;
        if (v) vmask |= (1u<<j);
    }
    if (ERASE){
        float t0 = g_thr[n*2+0], t1 = g_thr[n*2+1];
        #pragma unroll
        for (int j=0;j<NLD;j++){
            if ((vmask>>j)&1u){
                float s0 = seg[((size_t)(n*2+0))*HWSZ + off[j]];
                float s1 = seg[((size_t)(n*2+1))*HWSZ + off[j]];
                if (s0 > t0 || s1 > t1) emask |= (1u<<j);
            }
        }
    }

    {
        const float* src = img + (size_t)(n*3)*HWSZ;
        float rld[NLD];
        #pragma unroll
        for (int j=0;j<NLD;j++)
            rld[j] = (((vmask>>j)&1u) && !((emask>>j)&1u)) ? src[off[j]] : 0.f;
        float* tb = &tile[0][0][0];
        #pragma unroll
        for (int j=0;j<NLD;j++){ int i = tid + j*256; if (i < TSZ) tb[i] = rld[j]; }
    }
    __syncthreads();

    float acc[16][4];
    #pragma unroll
    for (int o=0;o<16;o++)
        #pragma unroll
        for (int k=0;k<4;k++) acc[o][k]=0.f;

    for (int c = 0; c < 3; c++){
        const int cur = c & 1;
        float rld[NLD];
        if (c+1 < 3){
            const float* src = img + (size_t)(n*3 + c+1)*HWSZ;
            #pragma unroll
            for (int j=0;j<NLD;j++)
                rld[j] = (((vmask>>j)&1u) && !((emask>>j)&1u)) ? src[off[j]] : 0.f;
        }
        #pragma unroll
        for (int r=0;r<3;r++)
        #pragma unroll
        for (int s=0;s<3;s++){
            float wv[16];
            #pragma unroll
            for (int o=0;o<16;o++) wv[o] = wsm[o*27 + c*9 + r*3 + s];
            #pragma unroll
            for (int k=0;k<4;k++){
                float v = tile[cur][ty + 8*k + r][tx + s];
                #pragma unroll
                for (int o=0;o<16;o++) acc[o][k] = fmaf(wv[o], v, acc[o][k]);
            }
        }
        if (c+1 < 3){
            float* tb = &tile[cur^1][0][0];
            #pragma unroll
            for (int j=0;j<NLD;j++){ int i = tid + j*256; if (i < TSZ) tb[i] = rld[j]; }
        }
        __syncthreads();
    }

    #pragma unroll
    for (int o=0;o<16;o++)
    #pragma unroll
    for (int k=0;k<4;k++){
        float v = fmaxf(acc[o][k], 0.f);
        size_t idx = (size_t)(y0+ty+8*k)*WW + x0 + tx;
        if (o < 8) feat[((size_t)(n*32 + oc0 + o  ))*HWSZ + idx] = v;
        else       aux [((size_t)(n*32 + oc0 + o-8))*HWSZ + idx] = v;
    }
}

// ---------------- 32->32 3x3 conv: 16 oc x 4 rows/thread, fused BN partials ----
// tile 32x32; 2 oc-groups; 4-buffer rotation: 2 channels per __syncthreads.
__global__ __launch_bounds__(256,2) void conv32_k(
    const float* __restrict__ in, const float* __restrict__ wt,
    float* __restrict__ out)
{
    __shared__ float tile[4][34][34];
    __shared__ float wsm[16*32*9];
    const int tid = threadIdx.y*32 + threadIdx.x;
    const int tx = threadIdx.x, ty = threadIdx.y;
    const int grp = blockIdx.z & 1;
    const int n   = blockIdx.z >> 1;
    const int oc0 = grp*16;
    const int x0 = blockIdx.x*32, y0 = blockIdx.y*32;
    const int TSZ = 34*34;
    const int NLD = 5;

    for (int i = tid; i < 16*32*9; i += 256) wsm[i] = wt[oc0*32*9 + i];

    int off[NLD]; unsigned vmask = 0u;
    #pragma unroll
    for (int j=0;j<NLD;j++){
        int i = tid + j*256;
        int yy = i/34, xx = i - yy*34;
        int gy = y0+yy-1, gx = x0+xx-1;
        bool v = (i < TSZ) && ((unsigned)gy < HH) && ((unsigned)gx < WW);
        off[j] = v ? (gy*WW + gx) : 0;
        if (v) vmask |= (1u<<j);
    }

    // load channels 0 and 1 into buffers 0 and 1
    {
        const float* s0 = in + (size_t)(n*32 + 0)*HWSZ;
        const float* s1 = in + (size_t)(n*32 + 1)*HWSZ;
        float rA[NLD], rB[NLD];
        #pragma unroll
        for (int j=0;j<NLD;j++){
            rA[j] = ((vmask>>j)&1u) ? s0[off[j]] : 0.f;
            rB[j] = ((vmask>>j)&1u) ? s1[off[j]] : 0.f;
        }
        float* tA = &tile[0][0][0];
        float* tB = &tile[1][0][0];
        #pragma unroll
        for (int j=0;j<NLD;j++){
            int i = tid + j*256;
            if (i < TSZ){ tA[i] = rA[j]; tB[i] = rB[j]; }
        }
    }
    __syncthreads();

    float acc[16][4];
    #pragma unroll
    for (int o=0;o<16;o++)
        #pragma unroll
        for (int k=0;k<4;k++) acc[o][k]=0.f;

    for (int c = 0; c < 32; c += 2){
        float rA[NLD], rB[NLD];
        if (c+2 < 32){
            const float* sA = in + (size_t)(n*32 + c+2)*HWSZ;
            const float* sB = in + (size_t)(n*32 + c+3)*HWSZ;
            #pragma unroll
            for (int j=0;j<NLD;j++){
                rA[j] = ((vmask>>j)&1u) ? sA[off[j]] : 0.f;
                rB[j] = ((vmask>>j)&1u) ? sB[off[j]] : 0.f;
            }
        }
        #pragma unroll
        for (int cc=0;cc<2;cc++){
            const int ch  = c + cc;
            const int buf = ch & 3;
            #pragma unroll
            for (int r=0;r<3;r++)
            #pragma unroll
            for (int s=0;s<3;s++){
                float wv[16];
                #pragma unroll
                for (int o=0;o<16;o++) wv[o] = wsm[(o*32+ch)*9 + r*3 + s];
                #pragma unroll
                for (int k=0;k<4;k++){
                    float v = tile[buf][ty + 8*k + r][tx + s];
                    #pragma unroll
                    for (int o=0;o<16;o++) acc[o][k] = fmaf(wv[o], v, acc[o][k]);
                }
            }
        }
        if (c+2 < 32){
            float* tA = &tile[(c+2)&3][0][0];
            float* tB = &tile[(c+3)&3][0][0];
            #pragma unroll
            for (int j=0;j<NLD;j++){
                int i = tid + j*256;
                if (i < TSZ){ tA[i] = rA[j]; tB[i] = rB[j]; }
            }
        }
        __syncthreads();
    }

    #pragma unroll
    for (int o=0;o<16;o++)
    #pragma unroll
    for (int k=0;k<4;k++)
        out[((size_t)(n*32 + oc0 + o))*HWSZ + (size_t)(y0+ty+8*k)*WW + x0 + tx] = acc[o][k];

    // deterministic per-block BN partials (one oc at a time: no reg blowup)
    float* red = &tile[0][0][0];
    #pragma unroll
    for (int o=0;o<16;o++){
        float sv=0.f, qv=0.f;
        #pragma unroll
        for (int k=0;k<4;k++){ float v=acc[o][k]; sv+=v; qv=fmaf(v,v,qv); }
        #pragma unroll
        for (int d=16; d>0; d>>=1){
            sv += __shfl_down_sync(0xffffffffu, sv, d);
            qv += __shfl_down_sync(0xffffffffu, qv, d);
        }
        if (tx == 0){ red[o*8+ty]=sv; red[128+o*8+ty]=qv; }
    }
    __syncthreads();
    if (tid < 16){
        float S=0.f, Q=0.f;
        #pragma unroll
        for (int w=0;w<8;w++){ S+=red[tid*8+w]; Q+=red[128+tid*8+w]; }
        int p = n*256 + blockIdx.y*gridDim.x + blockIdx.x;  // < 512
        g_part[((oc0+tid)*512+p)*2+0] = S;
        g_part[((oc0+tid)*512+p)*2+1] = Q;
    }
}

// ---------------- reduce conv32 partials (512/channel) -> scale1/shift1 --------
__global__ __launch_bounds__(256) void stats2_k(const float* __restrict__ g,
                                                const float* __restrict__ b)
{
    const int c = blockIdx.x;
    __shared__ float ss[256], qq[256];
    ss[threadIdx.x] = g_part[(c*512+threadIdx.x)*2+0] + g_part[(c*512+threadIdx.x+256)*2+0];
    qq[threadIdx.x] = g_part[(c*512+threadIdx.x)*2+1] + g_part[(c*512+threadIdx.x+256)*2+1];
    __syncthreads();
    for (int o=128;o>0;o>>=1){
        if (threadIdx.x < o){ ss[threadIdx.x]+=ss[threadIdx.x+o]; qq[threadIdx.x]+=qq[threadIdx.x+o]; }
        __syncthreads();
    }
    if (threadIdx.x==0){
        float mean = ss[0]/(float)NHW;
        float var  = qq[0]/(float)NHW - mean*mean;
        float sc = g[c]*rsqrtf(var + 1e-5f);
        g_scale1[c]=sc; g_shift1[c]=b[c]-mean*sc;
    }
}

// ---------------- z = sum_c relu(bn(auxb1_c)) * b2w_c, float4 (4 px/thread) ----
__global__ __launch_bounds__(256) void b2_k(const float* __restrict__ w2)
{
    __shared__ float s[32], h[32], ww[32];
    if (threadIdx.x < 32){ s[threadIdx.x]=g_scale1[threadIdx.x];
                           h[threadIdx.x]=g_shift1[threadIdx.x];
                           ww[threadIdx.x]=w2[threadIdx.x]; }
    __syncthreads();
    int base = (blockIdx.x*256 + threadIdx.x)*4;
    int n = base / HWSZ, r = base - n*HWSZ;
    float4 acc = make_float4(0.f,0.f,0.f,0.f);
    #pragma unroll
    for (int c=0;c<32;c++){
        float4 v = *(const float4*)&g_auxb1[((size_t)(n*32+c))*HWSZ + r];
        float sc = s[c], hc = h[c], wc = ww[c];
        acc.x = fmaf(fmaxf(fmaf(v.x,sc,hc),0.f), wc, acc.x);
        acc.y = fmaf(fmaxf(fmaf(v.y,sc,hc),0.f), wc, acc.y);
        acc.z = fmaf(fmaxf(fmaf(v.z,sc,hc),0.f), wc, acc.z);
        acc.w = fmaf(fmaxf(fmaf(v.w,sc,hc),0.f), wc, acc.w);
    }
    *(float4*)&g_z[base] = acc;
    float sv = acc.x + acc.y + acc.z + acc.w;
    float qv = fmaf(acc.x,acc.x, fmaf(acc.y,acc.y, fmaf(acc.z,acc.z, acc.w*acc.w)));
    __shared__ float ss[256], qq[256];
    ss[threadIdx.x]=sv; qq[threadIdx.x]=qv;
    __syncthreads();
    for (int o=128;o>0;o>>=1){
        if (threadIdx.x < o){ ss[threadIdx.x]+=ss[threadIdx.x+o]; qq[threadIdx.x]+=qq[threadIdx.x+o]; }
        __syncthreads();
    }
    if (threadIdx.x==0){
        g_part[blockIdx.x*2+0]=ss[0];
        g_part[blockIdx.x*2+1]=qq[0];
    }
}

// ---------------- x1 = conv(feat, w_out) ; inp = x1 + relu(bn(z)) --------------
// folded z-BN stats; 2px x 2rows per thread, float2 smem reads; tile 64x16
__global__ __launch_bounds__(256) void wout_inp_k(
    const float* __restrict__ feat, const float* __restrict__ wt,
    const float* __restrict__ b2g, const float* __restrict__ b2b)
{
    __shared__ float tile[2][18][68];
    __shared__ float wsm[32*9];
    __shared__ float rs[256], rq[256];
    const int tid = threadIdx.y*32 + threadIdx.x;
    const int tx = threadIdx.x, ty = threadIdx.y;
    const int n = blockIdx.z;
    const int x0 = blockIdx.x*64, y0 = blockIdx.y*16;
    const int TSZ = 18*66;
    const int NLD = 5;

    {
        float s = g_part[tid*2+0] + g_part[(tid+256)*2+0];
        float q = g_part[tid*2+1] + g_part[(tid+256)*2+1];
        rs[tid]=s; rq[tid]=q;
        __syncthreads();
        for (int o=128;o>0;o>>=1){
            if (tid < o){ rs[tid]+=rs[tid+o]; rq[tid]+=rq[tid+o]; }
            __syncthreads();
        }
        if (tid==0){
            float mean = rs[0]/(float)NHW;
            float var  = rq[0]/(float)NHW - mean*mean;
            float sc = b2g[0]*rsqrtf(var + 1e-5f);
            rs[0]=sc; rq[0]=b2b[0]-mean*sc;
        }
        __syncthreads();
    }
    const float s2 = rs[0], h2 = rq[0];

    for (int i = tid; i < 288; i += 256) wsm[i] = wt[i];

    int off[NLD]; unsigned vmask = 0u;
    #pragma unroll
    for (int j=0;j<NLD;j++){
        int i = tid + j*256;
        int yy = i/66, xx = i - yy*66;
        int gy = y0+yy-1, gx = x0+xx-1;
        bool v = (i < TSZ) && ((unsigned)gy < HH) && ((unsigned)gx < WW);
        off[j] = v ? (gy*WW + gx) : 0;
        if (v) vmask |= (1u<<j);
    }
    {
        const float* src = feat + (size_t)(n*32)*HWSZ;
        float rld[NLD];
        #pragma unroll
        for (int j=0;j<NLD;j++) rld[j] = ((vmask>>j)&1u) ? src[off[j]] : 0.f;
        float* tb = &tile[0][0][0];
        #pragma unroll
        for (int j=0;j<NLD;j++){
            int i = tid + j*256;
            if (i < TSZ){ int yy=i/66, xx=i-yy*66; tb[yy*68+xx] = rld[j]; }
        }
    }
    __syncthreads();

    float acc[2][2];
    acc[0][0]=acc[0][1]=acc[1][0]=acc[1][1]=0.f;

    for (int c = 0; c < 32; c++){
        const int cur = c & 1;
        float rld[NLD];
        if (c+1 < 32){
            const float* src = feat + (size_t)(n*32 + c+1)*HWSZ;
            #pragma unroll
            for (int j=0;j<NLD;j++) rld[j] = ((vmask>>j)&1u) ? src[off[j]] : 0.f;
        }
        #pragma unroll
        for (int r=0;r<3;r++){
            float w0 = wsm[c*9 + r*3 + 0];
            float w1 = wsm[c*9 + r*3 + 1];
            float w2 = wsm[c*9 + r*3 + 2];
            #pragma unroll
            for (int k=0;k<2;k++){
                const int row = ty + 8*k + r;
                float2 A = *(const float2*)&tile[cur][row][2*tx];
                float2 B = *(const float2*)&tile[cur][row][2*tx+2];
                acc[k][0] = fmaf(w0, A.x, acc[k][0]);
                acc[k][0] = fmaf(w1, A.y, acc[k][0]);
                acc[k][0] = fmaf(w2, B.x, acc[k][0]);
                acc[k][1] = fmaf(w0, A.y, acc[k][1]);
                acc[k][1] = fmaf(w1, B.x, acc[k][1]);
                acc[k][1] = fmaf(w2, B.y, acc[k][1]);
            }
        }
        if (c+1 < 32){
            float* tb = &tile[cur^1][0][0];
            #pragma unroll
            for (int j=0;j<NLD;j++){
                int i = tid + j*256;
                if (i < TSZ){ int yy=i/66, xx=i-yy*66; tb[yy*68+xx] = rld[j]; }
            }
        }
        __syncthreads();
    }

    #pragma unroll
    for (int k=0;k<2;k++){
        int idx = (y0+ty+8*k)*WW + x0 + 2*tx;
        float2 zz = *(const float2*)&g_z[(size_t)n*HWSZ + idx];
        float2 o;
        o.x = acc[k][0] + fmaxf(zz.x*s2 + h2, 0.f);
        o.y = acc[k][1] + fmaxf(zz.y*s2 + h2, 0.f);
        *(float2*)&g_inp[(size_t)n*HWSZ + idx] = o;
    }
}

// ---------------- xm25 = aff5(inp) + conv(xm9(inp), d1), xm9 fused -------------
__global__ __launch_bounds__(256) void xm25f_k(const float* __restrict__ d0,
                                               const float* __restrict__ d1)
{
    __shared__ float ti[12][68];
    __shared__ float t9[10][68];
    __shared__ float w0sm[81];
    __shared__ float w1sm[25*81];
    const int n = blockIdx.z;
    const int x0 = blockIdx.x*64, y0 = blockIdx.y*8;
    const int tid = threadIdx.y*32 + threadIdx.x;
    const int tx = threadIdx.x, ty = threadIdx.y;

    if (tid < 81) w0sm[tid] = d0[tid];
    for (int i=tid;i<25*81;i+=256) w1sm[i] = d1[i];
    for (int i=tid;i<12*68;i+=256){
        int yy=i/68, xx=i-yy*68;
        int gy=y0+yy-2, gx=x0+xx-2;
        ti[yy][xx] = ((unsigned)gy<HH && (unsigned)gx<WW) ? g_inp[(size_t)n*HWSZ + (size_t)gy*WW + gx] : 0.f;
    }
    __syncthreads();

    float acc[25][2];
    #pragma unroll
    for (int t=0;t<25;t++){ acc[t][0]=0.f; acc[t][1]=0.f; }

    for (int c=0;c<9;c++){
        const int ii = c/3, jj = c%3;
        float w0[9];
        #pragma unroll
        for (int u=0;u<9;u++) w0[u] = w0sm[c*9+u];
        for (int i=tid;i<10*66;i+=256){
            int yy=i/66, xx=i-yy*66;
            int gy=y0+yy-1, gx=x0+xx-1;
            float val = 0.f;
            if ((unsigned)gy<HH && (unsigned)gx<WW){
                float ctr = ti[yy+1][xx+1];
                val = ti[yy+ii][xx+jj]*ctr;
                #pragma unroll
                for (int r=0;r<3;r++)
                #pragma unroll
                for (int s=0;s<3;s++)
                    val = fmaf(ti[yy+r][xx+s], w0[r*3+s], val);
            }
            t9[yy][xx] = val;
        }
        __syncthreads();

        #pragma unroll
        for (int r=0;r<3;r++)
        #pragma unroll
        for (int s=0;s<3;s++){
            float v0 = t9[ty + r][tx + s];
            float v1 = t9[ty + r][tx + 32 + s];
            #pragma unroll
            for (int t=0;t<25;t++){
                float wv = w1sm[t*81 + c*9 + r*3 + s];
                acc[t][0] = fmaf(wv, v0, acc[t][0]);
                acc[t][1] = fmaf(wv, v1, acc[t][1]);
            }
        }
        __syncthreads();
    }

    #pragma unroll
    for (int t=0;t<25;t++){
        const int ai = t/5, aj = t%5;
        #pragma unroll
        for (int k=0;k<2;k++){
            int lx = tx + 32*k;
            float ctr = ti[ty+2][lx+2];
            float aff = ti[ty+ai][lx+aj] * ctr;
            g_xm25[((size_t)(n*25+t))*HWSZ + (size_t)(y0+ty)*WW + x0 + lx] = aff + acc[t][k];
        }
    }
}

// ---------------- conv4d + affinity reduce + seg output ------------------------
__global__ __launch_bounds__(256) void final_k(const float* __restrict__ d4,
                                               float* __restrict__ segout)
{
    __shared__ float t25[25][10][34];
    __shared__ float ti[12][36];
    __shared__ float wsm[81];
    const int n = blockIdx.z;
    const int x0 = blockIdx.x*32, y0 = blockIdx.y*8;
    const int tid = threadIdx.y*32 + threadIdx.x;
    if (tid < 81) wsm[tid] = d4[tid];
    for (int i = tid; i < 25*340; i += 256){
        int c = i/340, rr = i - c*340, yy = rr/34, xx = rr%34;
        int gy=y0+yy-1, gx=x0+xx-1;
        t25[c][yy][xx] = ((unsigned)gy<HH && (unsigned)gx<WW) ? g_xm25[((size_t)(n*25+c))*HWSZ + gy*WW + gx] : 0.f;
    }
    for (int i=tid;i<432;i+=256){
        int yy=i/36, xx=i%36;
        int gy=y0+yy-2, gx=x0+xx-2;
        ti[yy][xx] = ((unsigned)gy<HH && (unsigned)gx<WW) ? g_inp[(size_t)n*HWSZ + gy*WW + gx] : 0.f;
    }
    __syncthreads();

    float kacc[25];
    #pragma unroll
    for (int t=0;t<25;t++) kacc[t]=0.f;

    #pragma unroll
    for (int r=0;r<3;r++)
    #pragma unroll
    for (int s=0;s<3;s++){
        float wv[9];
        #pragma unroll
        for (int p=0;p<3;p++)
        #pragma unroll
        for (int q=0;q<3;q++) wv[p*3+q] = wsm[((p*3+q)*3+r)*3 + s];
        float L[25];
        #pragma unroll
        for (int u=0;u<5;u++)
        #pragma unroll
        for (int v=0;v<5;v++) L[u*5+v] = t25[u*5+v][threadIdx.y+r][threadIdx.x+s];
        #pragma unroll
        for (int d=0;d<5;d++)
        #pragma unroll
        for (int e=0;e<5;e++)
        #pragma unroll
        for (int p=0;p<3;p++){
            int u = d-1+p; if (u < 0 || u > 4) continue;
            #pragma unroll
            for (int q=0;q<3;q++){
                int v = e-1+q; if (v < 0 || v > 4) continue;
                kacc[d*5+e] = fmaf(L[u*5+v], wv[p*3+q], kacc[d*5+e]);
            }
        }
    }
    float sum = 0.f;
    #pragma unroll
    for (int ii=0;ii<5;ii++)
    #pragma unroll
    for (int jj=0;jj<5;jj++)
        sum = fmaf(ti[threadIdx.y+ii][threadIdx.x+jj], kacc[ii*5+jj], sum);

    float o = sum / 25.0f;
    int idx = (y0+threadIdx.y)*WW + x0 + threadIdx.x;
    segout[((size_t)(n*2+0))*HWSZ + idx] = 1.0f - o;
    segout[((size_t)(n*2+1))*HWSZ + idx] = o;
}

// ---------------- top-k threshold: 3-pass radix select (11/11/10 bits) ---------
__device__ __forceinline__ unsigned f2key(float f){
    unsigned u = __float_as_uint(f);
    return (u & 0x80000000u) ? ~u : (u | 0x80000000u);
}
__device__ __forceinline__ float key2f(unsigned k){
    unsigned u = (k & 0x80000000u) ? (k & 0x7fffffffu) : ~k;
    return __uint_as_float(u);
}

__global__ __launch_bounds__(256) void hist_k(const float* __restrict__ seg,
                                              int shift, int bins, unsigned mask)
{
    __shared__ unsigned hh[2048];
    const int j = blockIdx.y;
    for (int i = threadIdx.x; i < bins; i += 256) hh[i] = 0u;
    __syncthreads();
    const bool first = (mask == 0u);
    unsigned pfx = first ? 0u : g_prefix[j];
    const unsigned bm = (unsigned)(bins - 1);
    const float4* p = (const float4*)(seg + (size_t)j*HWSZ);
    for (int i = blockIdx.x*256 + threadIdx.x; i < HWSZ/4; i += 64*256){
        float4 v = p[i];
        unsigned k0 = f2key(v.x), k1 = f2key(v.y), k2 = f2key(v.z), k3 = f2key(v.w);
        if (first || (k0 & mask) == pfx) atomicAdd(&hh[(k0>>shift)&bm], 1u);
        if (first || (k1 & mask) == pfx) atomicAdd(&hh[(k1>>shift)&bm], 1u);
        if (first || (k2 & mask) == pfx) atomicAdd(&hh[(k2>>shift)&bm], 1u);
        if (first || (k3 & mask) == pfx) atomicAdd(&hh[(k3>>shift)&bm], 1u);
    }
    __syncthreads();
    for (int i = threadIdx.x; i < bins; i += 256)
        if (hh[i]) atomicAdd(&g_hist[j][i], hh[i]);
}

// 128 threads = 4 warps; warp j selects the digit for channel j.
__global__ void select_k(const float* __restrict__ ratio, int shift, int bins,
                         int first, int last)
{
    const int lane = threadIdx.x & 31;
    const int j    = threadIdx.x >> 5;
    int rem; unsigned pfx;
    if (first){
        int n = j >> 1;
        float fp = floorf(ratio[n]*(float)HWSZ);
        int k = (int)floorf(fp*0.1f);
        rem = k-1; if (rem < 0) rem = 0;
        pfx = 0u;
    } else { rem = g_remain[j]; pfx = g_prefix[j]; }

    const int C = bins >> 5;                 // bins per lane
    int lsum = 0;
    for (int b = lane*C; b < lane*C + C; b++) lsum += (int)g_hist[j][b];
    // inclusive suffix sum across lanes (lane l: sum over lanes >= l)
    int suf = lsum;
    #pragma unroll
    for (int d=1; d<32; d<<=1){
        int v = __shfl_down_sync(0xffffffffu, suf, d);
        if (lane + d < 32) suf += v;
    }
    int suf_next = __shfl_down_sync(0xffffffffu, suf, 1);
    if (lane == 31) suf_next = 0;
    bool mine = (suf > rem) && (suf_next <= rem);
    unsigned bal = __ballot_sync(0xffffffffu, mine);
    int src = __ffs(bal) - 1;
    int bsel = 0, newrem = 0;
    if (mine){
        int r2 = rem - suf_next;
        for (int b = lane*C + C - 1; b >= lane*C; b--){
            int cc = (int)g_hist[j][b];
            if (cc > r2){ bsel = b; newrem = r2; break; }
            r2 -= cc;
        }
    }
    bsel   = __shfl_sync(0xffffffffu, bsel,   src);
    newrem = __shfl_sync(0xffffffffu, newrem, src);
    pfx |= ((unsigned)bsel) << shift;
    if (lane == 0){
        g_prefix[j] = pfx; g_remain[j] = newrem;
        if (last) g_thr[j] = key2f(pfx);
    }
    __syncthreads();
    // clear all histogram bins for the next pass / next graph replay
    unsigned* hflat = &g_hist[0][0];
    for (int i = threadIdx.x; i < 4*2048; i += 128) hflat[i] = 0u;
}

// ---------------- host orchestration -------------------------------------------
struct Ptrs { float *feat, *aux, *auxb1; };

template<bool ERASE>
static void run_pipeline(const float* img, const float* seg, float* seg_out,
                         const float* w1, const float* wa, const float* wout,
                         const float* b1w, const float* b1g, const float* b1b,
                         const float* b2w, const float* b2g, const float* b2b,
                         const float* d0w, const float* d1w, const float* d4w,
                         const Ptrs& P)
{
    dim3 blk(32,8);
    dualconv3_k<ERASE><<<dim3(16,16,NB*4), blk>>>(img, seg, w1, wa, P.feat, P.aux);
    conv32_k<<<dim3(16,16,NB*2), blk>>>(P.aux, b1w, P.auxb1);
    stats2_k<<<32,256>>>(b1g, b1b);
    b2_k<<<NHW/1024, 256>>>(b2w);
    wout_inp_k<<<dim3(8,32,NB), blk>>>(P.feat, wout, b2g, b2b);
    xm25f_k<<<dim3(8,64,NB), blk>>>(d0w, d1w);
    final_k<<<dim3(16,64,NB), blk>>>(d4w, seg_out);
}

extern "C" void kernel_launch(void* const* d_in, const int* in_sizes, int n_in,
                              void* d_out, int out_size)
{
    const float* x     = (const float*)d_in[0];
    const float* ratio = (const float*)d_in[1];
    const float* w1    = (const float*)d_in[2];
    const float* wa    = (const float*)d_in[3];
    const float* wout  = (const float*)d_in[4];
    const float* b1w   = (const float*)d_in[5];
    const float* b1g   = (const float*)d_in[6];
    const float* b1b   = (const float*)d_in[7];
    const float* b2w   = (const float*)d_in[8];
    const float* b2g   = (const float*)d_in[9];
    const float* b2b   = (const float*)d_in[10];
    const float* d0w   = (const float*)d_in[11];
    const float* d1w   = (const float*)d_in[12];
    const float* d4w   = (const float*)d_in[13];
    float* out = (float*)d_out;

    Ptrs P;
    void* p;
    cudaGetSymbolAddress(&p, g_feat);   P.feat   = (float*)p;
    cudaGetSymbolAddress(&p, g_aux);    P.aux    = (float*)p;
    cudaGetSymbolAddress(&p, g_auxb1);  P.auxb1  = (float*)p;

    // pipeline 1 -> x1 (first half of output)
    run_pipeline<false>(x, nullptr, out, w1, wa, wout, b1w, b1g, b1b,
                        b2w, b2g, b2b, d0w, d1w, d4w, P);

    // erasing threshold: per-(n,c) 3-pass radix select (11/11/10 bits)
    const int      shifts[3] = {21, 10, 0};
    const int      binsv [3] = {2048, 2048, 1024};
    const unsigned masks [3] = {0u, 0xFFE00000u, 0xFFFFFC00u};
    for (int pass = 0; pass < 3; ++pass){
        hist_k<<<dim3(64,4), 256>>>(out, shifts[pass], binsv[pass], masks[pass]);
        select_k<<<1,128>>>(ratio, shifts[pass], binsv[pass],
                            pass==0 ? 1 : 0, pass==2 ? 1 : 0);
    }

    // pipeline 2 (erase fused into its dual conv3) -> x2 (second half)
    run_pipeline<true>(x, out, out + (size_t)NB*2*HWSZ, w1, wa, wout,
                       b1w, b1g, b1b, b2w, b2g, b2b, d0w, d1w, d4w, P);
}

// round 17
// speedup vs baseline: 1.9526x; 1.0024x over previous
#include <cuda_runtime.h>
#include <math.h>

#define HH 512
#define WW 512
#define NB 2
#define HWSZ (HH*WW)          // 262144
#define NHW (NB*HWSZ)         // 524288

// ---------------- scratch (device globals; no allocation allowed) -------------
__device__ float g_feat [NB*32*HWSZ];
__device__ float g_aux  [NB*32*HWSZ];
__device__ float g_auxb1[NB*32*HWSZ];
__device__ float g_z    [NHW];
__device__ float g_inp  [NHW];
__device__ float g_xm25 [NB*25*HWSZ];
__device__ float g_part [32*512*2];
__device__ float g_scale1[32], g_shift1[32];
__device__ unsigned g_hist[4][2048];
__device__ unsigned g_prefix[4];
__device__ int      g_remain[4];
__device__ float    g_thr[4];

// ---------------- fused dual 3x3 conv (3->32 twice): 16 oc x 4 rows/thread ----
template<bool ERASE>
__global__ __launch_bounds__(256) void dualconv3_k(
    const float* __restrict__ img, const float* __restrict__ seg,
    const float* __restrict__ w1, const float* __restrict__ wa,
    float* __restrict__ feat, float* __restrict__ aux)
{
    __shared__ float tile[2][34][34];
    __shared__ float wsm[16*27];
    const int tid = threadIdx.y*32 + threadIdx.x;
    const int tx = threadIdx.x, ty = threadIdx.y;
    const int grp = blockIdx.z & 3;
    const int n   = blockIdx.z >> 2;
    const int oc0 = grp*8;
    const int x0 = blockIdx.x*32, y0 = blockIdx.y*32;
    const int TSZ = 34*34;
    const int NLD = 5;

    for (int i = tid; i < 16*27; i += 256){
        int o = i/27, rr = i - o*27;
        wsm[i] = (o < 8) ? w1[(oc0+o)*27 + rr] : wa[(oc0+o-8)*27 + rr];
    }

    int off[NLD]; unsigned vmask = 0u, emask = 0u;
    #pragma unroll
    for (int j=0;j<NLD;j++){
        int i = tid + j*256;
        int yy = i/34, xx = i - yy*34;
        int gy = y0+yy-1, gx = x0+xx-1;
        bool v = (i < TSZ) && ((unsigned)gy < HH) && ((unsigned)gx < WW);
        off[j] = v ? (gy*WW + gx) : 0;
        if (v) vmask |= (1u<<j);
    }
    if (ERASE){
        // seg[n,0] == 1.0f - seg[n,1] bit-exactly; read only channel 2n+1.
        float t0 = g_thr[n*2+0], t1 = g_thr[n*2+1];
        #pragma unroll
        for (int j=0;j<NLD;j++){
            if ((vmask>>j)&1u){
                float s1 = seg[((size_t)(n*2+1))*HWSZ + off[j]];
                float s0 = 1.0f - s1;
                if (s0 > t0 || s1 > t1) emask |= (1u<<j);
            }
        }
    }

    {
        const float* src = img + (size_t)(n*3)*HWSZ;
        float rld[NLD];
        #pragma unroll
        for (int j=0;j<NLD;j++)
            rld[j] = (((vmask>>j)&1u) && !((emask>>j)&1u)) ? src[off[j]] : 0.f;
        float* tb = &tile[0][0][0];
        #pragma unroll
        for (int j=0;j<NLD;j++){ int i = tid + j*256; if (i < TSZ) tb[i] = rld[j]; }
    }
    __syncthreads();

    float acc[16][4];
    #pragma unroll
    for (int o=0;o<16;o++)
        #pragma unroll
        for (int k=0;k<4;k++) acc[o][k]=0.f;

    for (int c = 0; c < 3; c++){
        const int cur = c & 1;
        float rld[NLD];
        if (c+1 < 3){
            const float* src = img + (size_t)(n*3 + c+1)*HWSZ;
            #pragma unroll
            for (int j=0;j<NLD;j++)
                rld[j] = (((vmask>>j)&1u) && !((emask>>j)&1u)) ? src[off[j]] : 0.f;
        }
        #pragma unroll
        for (int r=0;r<3;r++)
        #pragma unroll
        for (int s=0;s<3;s++){
            float wv[16];
            #pragma unroll
            for (int o=0;o<16;o++) wv[o] = wsm[o*27 + c*9 + r*3 + s];
            #pragma unroll
            for (int k=0;k<4;k++){
                float v = tile[cur][ty + 8*k + r][tx + s];
                #pragma unroll
                for (int o=0;o<16;o++) acc[o][k] = fmaf(wv[o], v, acc[o][k]);
            }
        }
        if (c+1 < 3){
            float* tb = &tile[cur^1][0][0];
            #pragma unroll
            for (int j=0;j<NLD;j++){ int i = tid + j*256; if (i < TSZ) tb[i] = rld[j]; }
        }
        __syncthreads();
    }

    #pragma unroll
    for (int o=0;o<16;o++)
    #pragma unroll
    for (int k=0;k<4;k++){
        float v = fmaxf(acc[o][k], 0.f);
        size_t idx = (size_t)(y0+ty+8*k)*WW + x0 + tx;
        if (o < 8) feat[((size_t)(n*32 + oc0 + o  ))*HWSZ + idx] = v;
        else       aux [((size_t)(n*32 + oc0 + o-8))*HWSZ + idx] = v;
    }
}

// ---------------- 32->32 3x3 conv: 16 oc x 4 rows/thread, fused BN partials ----
// tile 32x32; 2 oc-groups; 4-buffer rotation: 2 channels per __syncthreads.
__global__ __launch_bounds__(256,2) void conv32_k(
    const float* __restrict__ in, const float* __restrict__ wt,
    float* __restrict__ out)
{
    __shared__ float tile[4][34][34];
    __shared__ float wsm[16*32*9];
    const int tid = threadIdx.y*32 + threadIdx.x;
    const int tx = threadIdx.x, ty = threadIdx.y;
    const int grp = blockIdx.z & 1;
    const int n   = blockIdx.z >> 1;
    const int oc0 = grp*16;
    const int x0 = blockIdx.x*32, y0 = blockIdx.y*32;
    const int TSZ = 34*34;
    const int NLD = 5;

    for (int i = tid; i < 16*32*9; i += 256) wsm[i] = wt[oc0*32*9 + i];

    int off[NLD]; unsigned vmask = 0u;
    #pragma unroll
    for (int j=0;j<NLD;j++){
        int i = tid + j*256;
        int yy = i/34, xx = i - yy*34;
        int gy = y0+yy-1, gx = x0+xx-1;
        bool v = (i < TSZ) && ((unsigned)gy < HH) && ((unsigned)gx < WW);
        off[j] = v ? (gy*WW + gx) : 0;
        if (v) vmask |= (1u<<j);
    }

    // load channels 0 and 1 into buffers 0 and 1
    {
        const float* s0 = in + (size_t)(n*32 + 0)*HWSZ;
        const float* s1 = in + (size_t)(n*32 + 1)*HWSZ;
        float rA[NLD], rB[NLD];
        #pragma unroll
        for (int j=0;j<NLD;j++){
            rA[j] = ((vmask>>j)&1u) ? s0[off[j]] : 0.f;
            rB[j] = ((vmask>>j)&1u) ? s1[off[j]] : 0.f;
        }
        float* tA = &tile[0][0][0];
        float* tB = &tile[1][0][0];
        #pragma unroll
        for (int j=0;j<NLD;j++){
            int i = tid + j*256;
            if (i < TSZ){ tA[i] = rA[j]; tB[i] = rB[j]; }
        }
    }
    __syncthreads();

    float acc[16][4];
    #pragma unroll
    for (int o=0;o<16;o++)
        #pragma unroll
        for (int k=0;k<4;k++) acc[o][k]=0.f;

    for (int c = 0; c < 32; c += 2){
        float rA[NLD], rB[NLD];
        if (c+2 < 32){
            const float* sA = in + (size_t)(n*32 + c+2)*HWSZ;
            const float* sB = in + (size_t)(n*32 + c+3)*HWSZ;
            #pragma unroll
            for (int j=0;j<NLD;j++){
                rA[j] = ((vmask>>j)&1u) ? sA[off[j]] : 0.f;
                rB[j] = ((vmask>>j)&1u) ? sB[off[j]] : 0.f;
            }
        }
        #pragma unroll
        for (int cc=0;cc<2;cc++){
            const int ch  = c + cc;
            const int buf = ch & 3;
            #pragma unroll
            for (int r=0;r<3;r++)
            #pragma unroll
            for (int s=0;s<3;s++){
                float wv[16];
                #pragma unroll
                for (int o=0;o<16;o++) wv[o] = wsm[(o*32+ch)*9 + r*3 + s];
                #pragma unroll
                for (int k=0;k<4;k++){
                    float v = tile[buf][ty + 8*k + r][tx + s];
                    #pragma unroll
                    for (int o=0;o<16;o++) acc[o][k] = fmaf(wv[o], v, acc[o][k]);
                }
            }
        }
        if (c+2 < 32){
            float* tA = &tile[(c+2)&3][0][0];
            float* tB = &tile[(c+3)&3][0][0];
            #pragma unroll
            for (int j=0;j<NLD;j++){
                int i = tid + j*256;
                if (i < TSZ){ tA[i] = rA[j]; tB[i] = rB[j]; }
            }
        }
        __syncthreads();
    }

    #pragma unroll
    for (int o=0;o<16;o++)
    #pragma unroll
    for (int k=0;k<4;k++)
        out[((size_t)(n*32 + oc0 + o))*HWSZ + (size_t)(y0+ty+8*k)*WW + x0 + tx] = acc[o][k];

    // deterministic per-block BN partials (one oc at a time: no reg blowup)
    float* red = &tile[0][0][0];
    #pragma unroll
    for (int o=0;o<16;o++){
        float sv=0.f, qv=0.f;
        #pragma unroll
        for (int k=0;k<4;k++){ float v=acc[o][k]; sv+=v; qv=fmaf(v,v,qv); }
        #pragma unroll
        for (int d=16; d>0; d>>=1){
            sv += __shfl_down_sync(0xffffffffu, sv, d);
            qv += __shfl_down_sync(0xffffffffu, qv, d);
        }
        if (tx == 0){ red[o*8+ty]=sv; red[128+o*8+ty]=qv; }
    }
    __syncthreads();
    if (tid < 16){
        float S=0.f, Q=0.f;
        #pragma unroll
        for (int w=0;w<8;w++){ S+=red[tid*8+w]; Q+=red[128+tid*8+w]; }
        int p = n*256 + blockIdx.y*gridDim.x + blockIdx.x;  // < 512
        g_part[((oc0+tid)*512+p)*2+0] = S;
        g_part[((oc0+tid)*512+p)*2+1] = Q;
    }
}

// ---------------- reduce conv32 partials (512/channel) -> scale1/shift1 --------
__global__ __launch_bounds__(256) void stats2_k(const float* __restrict__ g,
                                                const float* __restrict__ b)
{
    const int c = blockIdx.x;
    __shared__ float ss[256], qq[256];
    ss[threadIdx.x] = g_part[(c*512+threadIdx.x)*2+0] + g_part[(c*512+threadIdx.x+256)*2+0];
    qq[threadIdx.x] = g_part[(c*512+threadIdx.x)*2+1] + g_part[(c*512+threadIdx.x+256)*2+1];
    __syncthreads();
    for (int o=128;o>0;o>>=1){
        if (threadIdx.x < o){ ss[threadIdx.x]+=ss[threadIdx.x+o]; qq[threadIdx.x]+=qq[threadIdx.x+o]; }
        __syncthreads();
    }
    if (threadIdx.x==0){
        float mean = ss[0]/(float)NHW;
        float var  = qq[0]/(float)NHW - mean*mean;
        float sc = g[c]*rsqrtf(var + 1e-5f);
        g_scale1[c]=sc; g_shift1[c]=b[c]-mean*sc;
    }
}

// ---------------- z = sum_c relu(bn(auxb1_c)) * b2w_c, float4 (4 px/thread) ----
__global__ __launch_bounds__(256) void b2_k(const float* __restrict__ w2)
{
    __shared__ float s[32], h[32], ww[32];
    if (threadIdx.x < 32){ s[threadIdx.x]=g_scale1[threadIdx.x];
                           h[threadIdx.x]=g_shift1[threadIdx.x];
                           ww[threadIdx.x]=w2[threadIdx.x]; }
    __syncthreads();
    int base = (blockIdx.x*256 + threadIdx.x)*4;
    int n = base / HWSZ, r = base - n*HWSZ;
    float4 acc = make_float4(0.f,0.f,0.f,0.f);
    #pragma unroll
    for (int c=0;c<32;c++){
        float4 v = *(const float4*)&g_auxb1[((size_t)(n*32+c))*HWSZ + r];
        float sc = s[c], hc = h[c], wc = ww[c];
        acc.x = fmaf(fmaxf(fmaf(v.x,sc,hc),0.f), wc, acc.x);
        acc.y = fmaf(fmaxf(fmaf(v.y,sc,hc),0.f), wc, acc.y);
        acc.z = fmaf(fmaxf(fmaf(v.z,sc,hc),0.f), wc, acc.z);
        acc.w = fmaf(fmaxf(fmaf(v.w,sc,hc),0.f), wc, acc.w);
    }
    *(float4*)&g_z[base] = acc;
    float sv = acc.x + acc.y + acc.z + acc.w;
    float qv = fmaf(acc.x,acc.x, fmaf(acc.y,acc.y, fmaf(acc.z,acc.z, acc.w*acc.w)));
    __shared__ float ss[256], qq[256];
    ss[threadIdx.x]=sv; qq[threadIdx.x]=qv;
    __syncthreads();
    for (int o=128;o>0;o>>=1){
        if (threadIdx.x < o){ ss[threadIdx.x]+=ss[threadIdx.x+o]; qq[threadIdx.x]+=qq[threadIdx.x+o]; }
        __syncthreads();
    }
    if (threadIdx.x==0){
        g_part[blockIdx.x*2+0]=ss[0];
        g_part[blockIdx.x*2+1]=qq[0];
    }
}

// ---------------- x1 = conv(feat, w_out) ; inp = x1 + relu(bn(z)) --------------
// folded z-BN stats; 2px x 2rows per thread, float2 smem reads; tile 64x16
__global__ __launch_bounds__(256) void wout_inp_k(
    const float* __restrict__ feat, const float* __restrict__ wt,
    const float* __restrict__ b2g, const float* __restrict__ b2b)
{
    __shared__ float tile[2][18][68];
    __shared__ float wsm[32*9];
    __shared__ float rs[256], rq[256];
    const int tid = threadIdx.y*32 + threadIdx.x;
    const int tx = threadIdx.x, ty = threadIdx.y;
    const int n = blockIdx.z;
    const int x0 = blockIdx.x*64, y0 = blockIdx.y*16;
    const int TSZ = 18*66;
    const int NLD = 5;

    {
        float s = g_part[tid*2+0] + g_part[(tid+256)*2+0];
        float q = g_part[tid*2+1] + g_part[(tid+256)*2+1];
        rs[tid]=s; rq[tid]=q;
        __syncthreads();
        for (int o=128;o>0;o>>=1){
            if (tid < o){ rs[tid]+=rs[tid+o]; rq[tid]+=rq[tid+o]; }
            __syncthreads();
        }
        if (tid==0){
            float mean = rs[0]/(float)NHW;
            float var  = rq[0]/(float)NHW - mean*mean;
            float sc = b2g[0]*rsqrtf(var + 1e-5f);
            rs[0]=sc; rq[0]=b2b[0]-mean*sc;
        }
        __syncthreads();
    }
    const float s2 = rs[0], h2 = rq[0];

    for (int i = tid; i < 288; i += 256) wsm[i] = wt[i];

    int off[NLD]; unsigned vmask = 0u;
    #pragma unroll
    for (int j=0;j<NLD;j++){
        int i = tid + j*256;
        int yy = i/66, xx = i - yy*66;
        int gy = y0+yy-1, gx = x0+xx-1;
        bool v = (i < TSZ) && ((unsigned)gy < HH) && ((unsigned)gx < WW);
        off[j] = v ? (gy*WW + gx) : 0;
        if (v) vmask |= (1u<<j);
    }
    {
        const float* src = feat + (size_t)(n*32)*HWSZ;
        float rld[NLD];
        #pragma unroll
        for (int j=0;j<NLD;j++) rld[j] = ((vmask>>j)&1u) ? src[off[j]] : 0.f;
        float* tb = &tile[0][0][0];
        #pragma unroll
        for (int j=0;j<NLD;j++){
            int i = tid + j*256;
            if (i < TSZ){ int yy=i/66, xx=i-yy*66; tb[yy*68+xx] = rld[j]; }
        }
    }
    __syncthreads();

    float acc[2][2];
    acc[0][0]=acc[0][1]=acc[1][0]=acc[1][1]=0.f;

    for (int c = 0; c < 32; c++){
        const int cur = c & 1;
        float rld[NLD];
        if (c+1 < 32){
            const float* src = feat + (size_t)(n*32 + c+1)*HWSZ;
            #pragma unroll
            for (int j=0;j<NLD;j++) rld[j] = ((vmask>>j)&1u) ? src[off[j]] : 0.f;
        }
        #pragma unroll
        for (int r=0;r<3;r++){
            float w0 = wsm[c*9 + r*3 + 0];
            float w1 = wsm[c*9 + r*3 + 1];
            float w2 = wsm[c*9 + r*3 + 2];
            #pragma unroll
            for (int k=0;k<2;k++){
                const int row = ty + 8*k + r;
                float2 A = *(const float2*)&tile[cur][row][2*tx];
                float2 B = *(const float2*)&tile[cur][row][2*tx+2];
                acc[k][0] = fmaf(w0, A.x, acc[k][0]);
                acc[k][0] = fmaf(w1, A.y, acc[k][0]);
                acc[k][0] = fmaf(w2, B.x, acc[k][0]);
                acc[k][1] = fmaf(w0, A.y, acc[k][1]);
                acc[k][1] = fmaf(w1, B.x, acc[k][1]);
                acc[k][1] = fmaf(w2, B.y, acc[k][1]);
            }
        }
        if (c+1 < 32){
            float* tb = &tile[cur^1][0][0];
            #pragma unroll
            for (int j=0;j<NLD;j++){
                int i = tid + j*256;
                if (i < TSZ){ int yy=i/66, xx=i-yy*66; tb[yy*68+xx] = rld[j]; }
            }
        }
        __syncthreads();
    }

    #pragma unroll
    for (int k=0;k<2;k++){
        int idx = (y0+ty+8*k)*WW + x0 + 2*tx;
        float2 zz = *(const float2*)&g_z[(size_t)n*HWSZ + idx];
        float2 o;
        o.x = acc[k][0] + fmaxf(zz.x*s2 + h2, 0.f);
        o.y = acc[k][1] + fmaxf(zz.y*s2 + h2, 0.f);
        *(float2*)&g_inp[(size_t)n*HWSZ + idx] = o;
    }
}

// ---------------- xm25 = aff5(inp) + conv(xm9(inp), d1), xm9 fused -------------
__global__ __launch_bounds__(256) void xm25f_k(const float* __restrict__ d0,
                                               const float* __restrict__ d1)
{
    __shared__ float ti[12][68];
    __shared__ float t9[10][68];
    __shared__ float w0sm[81];
    __shared__ float w1sm[25*81];
    const int n = blockIdx.z;
    const int x0 = blockIdx.x*64, y0 = blockIdx.y*8;
    const int tid = threadIdx.y*32 + threadIdx.x;
    const int tx = threadIdx.x, ty = threadIdx.y;

    if (tid < 81) w0sm[tid] = d0[tid];
    for (int i=tid;i<25*81;i+=256) w1sm[i] = d1[i];
    for (int i=tid;i<12*68;i+=256){
        int yy=i/68, xx=i-yy*68;
        int gy=y0+yy-2, gx=x0+xx-2;
        ti[yy][xx] = ((unsigned)gy<HH && (unsigned)gx<WW) ? g_inp[(size_t)n*HWSZ + (size_t)gy*WW + gx] : 0.f;
    }
    __syncthreads();

    float acc[25][2];
    #pragma unroll
    for (int t=0;t<25;t++){ acc[t][0]=0.f; acc[t][1]=0.f; }

    for (int c=0;c<9;c++){
        const int ii = c/3, jj = c%3;
        float w0[9];
        #pragma unroll
        for (int u=0;u<9;u++) w0[u] = w0sm[c*9+u];
        for (int i=tid;i<10*66;i+=256){
            int yy=i/66, xx=i-yy*66;
            int gy=y0+yy-1, gx=x0+xx-1;
            float val = 0.f;
            if ((unsigned)gy<HH && (unsigned)gx<WW){
                float ctr = ti[yy+1][xx+1];
                val = ti[yy+ii][xx+jj]*ctr;
                #pragma unroll
                for (int r=0;r<3;r++)
                #pragma unroll
                for (int s=0;s<3;s++)
                    val = fmaf(ti[yy+r][xx+s], w0[r*3+s], val);
            }
            t9[yy][xx] = val;
        }
        __syncthreads();

        #pragma unroll
        for (int r=0;r<3;r++)
        #pragma unroll
        for (int s=0;s<3;s++){
            float v0 = t9[ty + r][tx + s];
            float v1 = t9[ty + r][tx + 32 + s];
            #pragma unroll
            for (int t=0;t<25;t++){
                float wv = w1sm[t*81 + c*9 + r*3 + s];
                acc[t][0] = fmaf(wv, v0, acc[t][0]);
                acc[t][1] = fmaf(wv, v1, acc[t][1]);
            }
        }
        __syncthreads();
    }

    #pragma unroll
    for (int t=0;t<25;t++){
        const int ai = t/5, aj = t%5;
        #pragma unroll
        for (int k=0;k<2;k++){
            int lx = tx + 32*k;
            float ctr = ti[ty+2][lx+2];
            float aff = ti[ty+ai][lx+aj] * ctr;
            g_xm25[((size_t)(n*25+t))*HWSZ + (size_t)(y0+ty)*WW + x0 + lx] = aff + acc[t][k];
        }
    }
}

// ---------------- conv4d + affinity reduce + seg output ------------------------
__global__ __launch_bounds__(256) void final_k(const float* __restrict__ d4,
                                               float* __restrict__ segout)
{
    __shared__ float t25[25][10][34];
    __shared__ float ti[12][36];
    __shared__ float wsm[81];
    const int n = blockIdx.z;
    const int x0 = blockIdx.x*32, y0 = blockIdx.y*8;
    const int tid = threadIdx.y*32 + threadIdx.x;
    if (tid < 81) wsm[tid] = d4[tid];
    for (int i = tid; i < 25*340; i += 256){
        int c = i/340, rr = i - c*340, yy = rr/34, xx = rr%34;
        int gy=y0+yy-1, gx=x0+xx-1;
        t25[c][yy][xx] = ((unsigned)gy<HH && (unsigned)gx<WW) ? g_xm25[((size_t)(n*25+c))*HWSZ + gy*WW + gx] : 0.f;
    }
    for (int i=tid;i<432;i+=256){
        int yy=i/36, xx=i%36;
        int gy=y0+yy-2, gx=x0+xx-2;
        ti[yy][xx] = ((unsigned)gy<HH && (unsigned)gx<WW) ? g_inp[(size_t)n*HWSZ + gy*WW + gx] : 0.f;
    }
    __syncthreads();

    float kacc[25];
    #pragma unroll
    for (int t=0;t<25;t++) kacc[t]=0.f;

    #pragma unroll
    for (int r=0;r<3;r++)
    #pragma unroll
    for (int s=0;s<3;s++){
        float wv[9];
        #pragma unroll
        for (int p=0;p<3;p++)
        #pragma unroll
        for (int q=0;q<3;q++) wv[p*3+q] = wsm[((p*3+q)*3+r)*3 + s];
        float L[25];
        #pragma unroll
        for (int u=0;u<5;u++)
        #pragma unroll
        for (int v=0;v<5;v++) L[u*5+v] = t25[u*5+v][threadIdx.y+r][threadIdx.x+s];
        #pragma unroll
        for (int d=0;d<5;d++)
        #pragma unroll
        for (int e=0;e<5;e++)
        #pragma unroll
        for (int p=0;p<3;p++){
            int u = d-1+p; if (u < 0 || u > 4) continue;
            #pragma unroll
            for (int q=0;q<3;q++){
                int v = e-1+q; if (v < 0 || v > 4) continue;
                kacc[d*5+e] = fmaf(L[u*5+v], wv[p*3+q], kacc[d*5+e]);
            }
        }
    }
    float sum = 0.f;
    #pragma unroll
    for (int ii=0;ii<5;ii++)
    #pragma unroll
    for (int jj=0;jj<5;jj++)
        sum = fmaf(ti[threadIdx.y+ii][threadIdx.x+jj], kacc[ii*5+jj], sum);

    float o = sum / 25.0f;
    int idx = (y0+threadIdx.y)*WW + x0 + threadIdx.x;
    segout[((size_t)(n*2+0))*HWSZ + idx] = 1.0f - o;
    segout[((size_t)(n*2+1))*HWSZ + idx] = o;
}

// ---------------- top-k threshold: 3-pass radix select (11/11/10 bits) ---------
__device__ __forceinline__ unsigned f2key(float f){
    unsigned u = __float_as_uint(f);
    return (u & 0x80000000u) ? ~u : (u | 0x80000000u);
}
__device__ __forceinline__ float key2f(unsigned k){
    unsigned u = (k & 0x80000000u) ? (k & 0x7fffffffu) : ~k;
    return __uint_as_float(u);
}

// even channels derive values as 1.0f - (odd channel) — bit-exact, halves traffic
__global__ __launch_bounds__(256) void hist_k(const float* __restrict__ seg,
                                              int shift, int bins, unsigned mask)
{
    __shared__ unsigned hh[2048];
    const int j = blockIdx.y;
    for (int i = threadIdx.x; i < bins; i += 256) hh[i] = 0u;
    __syncthreads();
    const bool first = (mask == 0u);
    const bool comp  = ((j & 1) == 0);          // complement channel
    unsigned pfx = first ? 0u : g_prefix[j];
    const unsigned bm = (unsigned)(bins - 1);
    const float4* p = (const float4*)(seg + (size_t)(j | 1)*HWSZ);
    for (int i = blockIdx.x*256 + threadIdx.x; i < HWSZ/4; i += 64*256){
        float4 v = p[i];
        if (comp){ v.x = 1.0f - v.x; v.y = 1.0f - v.y; v.z = 1.0f - v.z; v.w = 1.0f - v.w; }
        unsigned k0 = f2key(v.x), k1 = f2key(v.y), k2 = f2key(v.z), k3 = f2key(v.w);
        if (first || (k0 & mask) == pfx) atomicAdd(&hh[(k0>>shift)&bm], 1u);
        if (first || (k1 & mask) == pfx) atomicAdd(&hh[(k1>>shift)&bm], 1u);
        if (first || (k2 & mask) == pfx) atomicAdd(&hh[(k2>>shift)&bm], 1u);
        if (first || (k3 & mask) == pfx) atomicAdd(&hh[(k3>>shift)&bm], 1u);
    }
    __syncthreads();
    for (int i = threadIdx.x; i < bins; i += 256)
        if (hh[i]) atomicAdd(&g_hist[j][i], hh[i]);
}

// 128 threads = 4 warps; warp j selects the digit for channel j.
__global__ void select_k(const float* __restrict__ ratio, int shift, int bins,
                         int first, int last)
{
    const int lane = threadIdx.x & 31;
    const int j    = threadIdx.x >> 5;
    int rem; unsigned pfx;
    if (first){
        int n = j >> 1;
        float fp = floorf(ratio[n]*(float)HWSZ);
        int k = (int)floorf(fp*0.1f);
        rem = k-1; if (rem < 0) rem = 0;
        pfx = 0u;
    } else { rem = g_remain[j]; pfx = g_prefix[j]; }

    const int C = bins >> 5;                 // bins per lane
    int lsum = 0;
    for (int b = lane*C; b < lane*C + C; b++) lsum += (int)g_hist[j][b];
    int suf = lsum;
    #pragma unroll
    for (int d=1; d<32; d<<=1){
        int v = __shfl_down_sync(0xffffffffu, suf, d);
        if (lane + d < 32) suf += v;
    }
    int suf_next = __shfl_down_sync(0xffffffffu, suf, 1);
    if (lane == 31) suf_next = 0;
    bool mine = (suf > rem) && (suf_next <= rem);
    unsigned bal = __ballot_sync(0xffffffffu, mine);
    int src = __ffs(bal) - 1;
    int bsel = 0, newrem = 0;
    if (mine){
        int r2 = rem - suf_next;
        for (int b = lane*C + C - 1; b >= lane*C; b--){
            int cc = (int)g_hist[j][b];
            if (cc > r2){ bsel = b; newrem = r2; break; }
            r2 -= cc;
        }
    }
    bsel   = __shfl_sync(0xffffffffu, bsel,   src);
    newrem = __shfl_sync(0xffffffffu, newrem, src);
    pfx |= ((unsigned)bsel) << shift;
    if (lane == 0){
        g_prefix[j] = pfx; g_remain[j] = newrem;
        if (last) g_thr[j] = key2f(pfx);
    }
    __syncthreads();
    unsigned* hflat = &g_hist[0][0];
    for (int i = threadIdx.x; i < 4*2048; i += 128) hflat[i] = 0u;
}

// ---------------- host orchestration -------------------------------------------
struct Ptrs { float *feat, *aux, *auxb1; };

template<bool ERASE>
static void run_pipeline(const float* img, const float* seg, float* seg_out,
                         const float* w1, const float* wa, const float* wout,
                         const float* b1w, const float* b1g, const float* b1b,
                         const float* b2w, const float* b2g, const float* b2b,
                         const float* d0w, const float* d1w, const float* d4w,
                         const Ptrs& P)
{
    dim3 blk(32,8);
    dualconv3_k<ERASE><<<dim3(16,16,NB*4), blk>>>(img, seg, w1, wa, P.feat, P.aux);
    conv32_k<<<dim3(16,16,NB*2), blk>>>(P.aux, b1w, P.auxb1);
    stats2_k<<<32,256>>>(b1g, b1b);
    b2_k<<<NHW/1024, 256>>>(b2w);
    wout_inp_k<<<dim3(8,32,NB), blk>>>(P.feat, wout, b2g, b2b);
    xm25f_k<<<dim3(8,64,NB), blk>>>(d0w, d1w);
    final_k<<<dim3(16,64,NB), blk>>>(d4w, seg_out);
}

extern "C" void kernel_launch(void* const* d_in, const int* in_sizes, int n_in,
                              void* d_out, int out_size)
{
    const float* x     = (const float*)d_in[0];
    const float* ratio = (const float*)d_in[1];
    const float* w1    = (const float*)d_in[2];
    const float* wa    = (const float*)d_in[3];
    const float* wout  = (const float*)d_in[4];
    const float* b1w   = (const float*)d_in[5];
    const float* b1g   = (const float*)d_in[6];
    const float* b1b   = (const float*)d_in[7];
    const float* b2w   = (const float*)d_in[8];
    const float* b2g   = (const float*)d_in[9];
    const float* b2b   = (const float*)d_in[10];
    const float* d0w   = (const float*)d_in[11];
    const float* d1w   = (const float*)d_in[12];
    const float* d4w   = (const float*)d_in[13];
    float* out = (float*)d_out;

    Ptrs P;
    void* p;
    cudaGetSymbolAddress(&p, g_feat);   P.feat   = (float*)p;
    cudaGetSymbolAddress(&p, g_aux);    P.aux    = (float*)p;
    cudaGetSymbolAddress(&p, g_auxb1);  P.auxb1  = (float*)p;

    // pipeline 1 -> x1 (first half of output)
    run_pipeline<false>(x, nullptr, out, w1, wa, wout, b1w, b1g, b1b,
                        b2w, b2g, b2b, d0w, d1w, d4w, P);

    // erasing threshold: per-(n,c) 3-pass radix select (11/11/10 bits)
    const int      shifts[3] = {21, 10, 0};
    const int      binsv [3] = {2048, 2048, 1024};
    const unsigned masks [3] = {0u, 0xFFE00000u, 0xFFFFFC00u};
    for (int pass = 0; pass < 3; ++pass){
        hist_k<<<dim3(64,4), 256>>>(out, shifts[pass], binsv[pass], masks[pass]);
        select_k<<<1,128>>>(ratio, shifts[pass], binsv[pass],
                            pass==0 ? 1 : 0, pass==2 ? 1 : 0);
    }

    // pipeline 2 (erase fused into its dual conv3) -> x2 (second half)
    run_pipeline<true>(x, out, out + (size_t)NB*2*HWSZ, w1, wa, wout,
                       b1w, b1g, b1b, b2w, b2g, b2b, d0w, d1w, d4w, P);
}